// round 10
// baseline (speedup 1.0000x reference)
#include <cuda_runtime.h>
#include <cuda_bf16.h>
#include <cuda_fp8.h>
#include <cstdint>

constexpr int kL  = 4096;
constexpr int kD  = 1024;
constexpr int kDI = 2048;
constexpr int kM  = 4 * kL;           // 16384
constexpr int kDS = 16;

// scales for fp8
constexpr float SW   = 64.f;          // weight scale
constexpr float SB1  = 64.f;          // b1 activation scale
constexpr float SY2  = 256.f;         // y2 activation scale
constexpr float INV_IN   = 1.f / SW;            // in-proj: hn(1) * w(64)
constexpr float INV_FUSE = 1.f / (SB1 * SW);    // fuse: b1(64) * W3(64)
constexpr float INV_OUT  = 1.f / (SY2 * SW);    // out: y2(256) * w_out(64)

// ---------------- static scratch ----------------
__device__ __align__(256) uint8_t       g_hn8 [(size_t)kM * kD];
__device__ __align__(256) __nv_bfloat16 g_gate[(size_t)kM * kDI];
__device__ __align__(256) __nv_bfloat16 g_val [(size_t)kM * kDI];
__device__ __align__(256) __nv_bfloat16 g_a1  [(size_t)kM * kDI];
__device__ __align__(256) float         g_a2  [(size_t)kM * kDS];
__device__ __align__(256) float         g_C1  [(size_t)kDS * kD];
__device__ __align__(256) float         g_C2  [(size_t)kDS * kDI];
__device__ __align__(256) uint8_t       g_b18 [(size_t)kM * kDI];
__device__ __align__(256) __nv_bfloat16 g_az  [(size_t)kM * kDI];
__device__ __align__(256) uint8_t       g_y28 [(size_t)kM * kDI];
__device__ __align__(256) uint8_t       g_w_in8 [(size_t)2*kDI * kD];
__device__ __align__(256) uint8_t       g_w_out8[(size_t)kD * kDI];
__device__ __align__(256) uint8_t       g_W38   [(size_t)kDI * kDI];
__device__ __align__(256) __nv_bfloat16 g_w_fuse[(size_t)kDI * kDI];   // bf16 fuse_w (precompute)
__device__ __align__(256) __nv_bfloat16 g_hbT [(size_t)kDI * kD];
__device__ __align__(256) __nv_bfloat16 g_pwT [(size_t)kDI * kDI];
__device__ __align__(256) __nv_bfloat16 g_W2  [(size_t)kDI * kDI];
__device__ __align__(256) __nv_bfloat16 g_W3  [(size_t)kDI * kDI];
__device__ float g_zb[kDI];
__device__ float g_zero_bias[kDI];

#define DEVFN __device__ __forceinline__

DEVFN void cp_async16(void* smem, const void* gmem) {
    uint32_t a = (uint32_t)__cvta_generic_to_shared(smem);
    asm volatile("cp.async.cg.shared.global [%0], [%1], 16;" :: "r"(a), "l"(gmem));
}
DEVFN void cp_commit() { asm volatile("cp.async.commit_group;"); }
template<int N> DEVFN void cp_wait_group() { asm volatile("cp.async.wait_group %0;" :: "n"(N)); }
DEVFN uint8_t f2e4m3(float v) {
    return (uint8_t)__nv_cvt_float_to_fp8(v, __NV_SATFINITE, __NV_E4M3);
}

// ---------------- conversion / elementwise kernels ----------------
__global__ void f2bf_kernel(const float4* __restrict__ s, uint2* __restrict__ d, int n4) {
    int i = blockIdx.x * blockDim.x + threadIdx.x, st = gridDim.x * blockDim.x;
    for (; i < n4; i += st) {
        float4 v = s[i];
        __nv_bfloat162 lo = __floats2bfloat162_rn(v.x, v.y);
        __nv_bfloat162 hi = __floats2bfloat162_rn(v.z, v.w);
        uint2 o; o.x = *(uint32_t*)&lo; o.y = *(uint32_t*)&hi;
        d[i] = o;
    }
}

// fp32 -> fp8 with scale
__global__ void f2f8_kernel(const float4* __restrict__ s, uint32_t* __restrict__ d, int n4, float sc) {
    int i = blockIdx.x * blockDim.x + threadIdx.x, st = gridDim.x * blockDim.x;
    for (; i < n4; i += st) {
        float4 v = s[i];
        uint32_t o = (uint32_t)f2e4m3(v.x * sc) | ((uint32_t)f2e4m3(v.y * sc) << 8)
                   | ((uint32_t)f2e4m3(v.z * sc) << 16) | ((uint32_t)f2e4m3(v.w * sc) << 24);
        d[i] = o;
    }
}

// bf16 -> fp8 with scale
__global__ void bf2f8_kernel(const __nv_bfloat16* __restrict__ s, uint32_t* __restrict__ d,
                             int n4, float sc) {
    int i = blockIdx.x * blockDim.x + threadIdx.x, st = gridDim.x * blockDim.x;
    for (; i < n4; i += st) {
        const __nv_bfloat16* p = s + (size_t)i * 4;
        uint32_t o = (uint32_t)f2e4m3(__bfloat162float(p[0]) * sc)
                   | ((uint32_t)f2e4m3(__bfloat162float(p[1]) * sc) << 8)
                   | ((uint32_t)f2e4m3(__bfloat162float(p[2]) * sc) << 16)
                   | ((uint32_t)f2e4m3(__bfloat162float(p[3]) * sc) << 24);
        d[i] = o;
    }
}

// transpose fp32 [R,C] -> bf16 [C,R]
__global__ void transpose_f2bf(const float* __restrict__ src, __nv_bfloat16* __restrict__ dst,
                               int R, int C) {
    __shared__ float t[32][33];
    int c0 = blockIdx.x * 32, r0 = blockIdx.y * 32;
    int x = threadIdx.x;
    #pragma unroll
    for (int y = threadIdx.y; y < 32; y += 8)
        t[y][x] = src[(size_t)(r0 + y) * C + c0 + x];
    __syncthreads();
    #pragma unroll
    for (int y = threadIdx.y; y < 32; y += 8)
        dst[(size_t)(c0 + y) * R + r0 + x] = __float2bfloat16(t[x][y]);
}

// rmsnorm: fp32 in -> fp8 out (scale 1)
__global__ void rmsnorm_kernel(const float* __restrict__ x, const float* __restrict__ w,
                               uint8_t* __restrict__ out) {
    int m = blockIdx.x;
    const float* xr = x + (size_t)m * kD;
    float ss = 0.f;
    for (int c = threadIdx.x; c < kD; c += 256) { float v = xr[c]; ss += v * v; }
    #pragma unroll
    for (int o = 16; o; o >>= 1) ss += __shfl_xor_sync(~0u, ss, o);
    __shared__ float red[8];
    if ((threadIdx.x & 31) == 0) red[threadIdx.x >> 5] = ss;
    __syncthreads();
    float tot = 0.f;
    #pragma unroll
    for (int i = 0; i < 8; ++i) tot += red[i];
    float sc = rsqrtf(tot * (1.f / kD) + 1e-6f);
    for (int c = threadIdx.x; c < kD; c += 256)
        out[(size_t)m * kD + c] = f2e4m3(w[c] * xr[c] * sc);
}

// fused depthwise convs: a1 = conv4(val) (bf16), b1 = silu(conv9(val)) (fp8 * SB1)
__global__ void dwconv_fused_kernel(const __nv_bfloat16* __restrict__ val,
                                    const float* __restrict__ k4, const float* __restrict__ b4,
                                    const float* __restrict__ k9, const float* __restrict__ b9,
                                    __nv_bfloat16* __restrict__ a1, uint8_t* __restrict__ b1) {
    int idx = blockIdx.x * blockDim.x + threadIdx.x;
    int c = idx & (kDI - 1);
    int m = idx >> 11;
    int l = m & (kL - 1);
    float v[9];
    #pragma unroll
    for (int t = 0; t < 9; ++t) {
        int ll = l + t - 4;
        v[t] = (ll >= 0 && ll < kL) ? __bfloat162float(val[(size_t)(m + t - 4) * kDI + c]) : 0.f;
    }
    float a = b4[c];
    #pragma unroll
    for (int t = 0; t < 4; ++t) a += v[t + 3] * k4[c * 4 + t];
    float b = b9[c];
    #pragma unroll
    for (int t = 0; t < 9; ++t) b += v[t] * k9[c * 9 + t];
    a1[idx] = __float2bfloat16(a);
    b1[idx] = f2e4m3((b / (1.f + __expf(-b))) * SB1);
}

__global__ void lowrank_a2_kernel(const __nv_bfloat16* __restrict__ a1,
                                  const float* __restrict__ A, float* __restrict__ a2) {
    int warp = (blockIdx.x * blockDim.x + threadIdx.x) >> 5;
    int lane = threadIdx.x & 31;
    if (warp >= kM) return;
    float acc[kDS];
    #pragma unroll
    for (int s = 0; s < kDS; ++s) acc[s] = 0.f;
    const __nv_bfloat16* row = a1 + (size_t)warp * kDI;
    for (int c = lane; c < kDI; c += 32) {
        float av = __bfloat162float(row[c]);
        const float* Ac = A + (size_t)c * kDS;
        #pragma unroll
        for (int s = 0; s < kDS; ++s) acc[s] += av * Ac[s];
    }
    #pragma unroll
    for (int s = 0; s < kDS; ++s) {
        #pragma unroll
        for (int o = 16; o; o >>= 1) acc[s] += __shfl_xor_sync(~0u, acc[s], o);
    }
    if (lane == 0) {
        #pragma unroll
        for (int s = 0; s < kDS; ++s) a2[(size_t)warp * kDS + s] = acc[s];
    }
}

__global__ void c1_kernel(const float* __restrict__ Bm, const float* __restrict__ ha_w,
                          float* __restrict__ C1) {
    int g = (blockIdx.x * blockDim.x + threadIdx.x) >> 5;
    int lane = threadIdx.x & 31;
    if (g >= kDS * kD) return;
    int s = g >> 10, h = g & 1023;
    float acc = 0.f;
    const float* br = Bm + (size_t)s * kDI;
    const float* hr = ha_w + (size_t)h * kDI;
    for (int d = lane; d < kDI; d += 32) acc += br[d] * hr[d];
    #pragma unroll
    for (int o = 16; o; o >>= 1) acc += __shfl_xor_sync(~0u, acc, o);
    if (lane == 0) C1[(size_t)s * kD + h] = acc;
}

__global__ void c2_kernel(const float* __restrict__ C1, const float* __restrict__ fuse_w,
                          float* __restrict__ C2) {
    int g = (blockIdx.x * blockDim.x + threadIdx.x) >> 5;
    int lane = threadIdx.x & 31;
    if (g >= kDS * kDI) return;
    int s = g >> 11, o = g & (kDI - 1);
    float acc = 0.f;
    const float* cr = C1 + (size_t)s * kD;
    const float* fr = fuse_w + (size_t)o * kDI;
    for (int h = lane; h < kD; h += 32) acc += cr[h] * fr[h];
    #pragma unroll
    for (int q = 16; q; q >>= 1) acc += __shfl_xor_sync(~0u, acc, q);
    if (lane == 0) C2[(size_t)s * kDI + o] = acc;
}

__global__ void zbias_kernel(const float* __restrict__ fuse_b, const float* __restrict__ ha_b,
                             const float* __restrict__ hb_b, const float* __restrict__ pw_b,
                             const float* __restrict__ fuse_w, const __nv_bfloat16* __restrict__ W2,
                             float* __restrict__ zb) {
    int o = (blockIdx.x * blockDim.x + threadIdx.x) >> 5;
    int lane = threadIdx.x & 31;
    if (o >= kDI) return;
    float acc = 0.f;
    const float* fr = fuse_w + (size_t)o * kDI;
    for (int h = lane; h < kD; h += 32) acc += ha_b[h] * fr[h] + hb_b[h] * fr[kD + h];
    const __nv_bfloat16* wr = W2 + (size_t)o * kDI;
    for (int d = lane; d < kDI; d += 32) acc += pw_b[d] * __bfloat162float(wr[d]);
    #pragma unroll
    for (int q = 16; q; q >>= 1) acc += __shfl_xor_sync(~0u, acc, q);
    if (lane == 0) zb[o] = fuse_b[o] + acc;
}

__global__ void aadd_kernel(const float* __restrict__ a2, const float* __restrict__ C2,
                            __nv_bfloat16* __restrict__ az) {
    int idx = blockIdx.x * blockDim.x + threadIdx.x;
    int o = idx & (kDI - 1), m = idx >> 11;
    float acc = 0.f;
    const float* ar = a2 + (size_t)m * kDS;
    #pragma unroll
    for (int s = 0; s < kDS; ++s) acc += ar[s] * C2[(size_t)s * kDI + o];
    az[idx] = __float2bfloat16(acc);
}

// ==================== bf16 GEMM (precompute only, MODE0) ====================
constexpr int BM = 128, BN = 256;
constexpr int BKH = 64, LDSH = BKH + 8;
constexpr int NROWS = BM + BN;
constexpr int NSTG  = 3;
constexpr int STG_ELEMS = NROWS * LDSH;
constexpr size_t SMEM_G = (size_t)NSTG * STG_ELEMS * 2;     // 165888 B

__global__ __launch_bounds__(256, 1)
void gemm_bf16_pre(const __nv_bfloat16* __restrict__ Ag,
                   const __nv_bfloat16* __restrict__ Bg,
                   int K, int lda, int ldb,
                   __nv_bfloat16* __restrict__ out0, int ldc) {
    extern __shared__ __align__(16) __nv_bfloat16 sm[];
    const int tid = threadIdx.x, lane = tid & 31, warp = tid >> 5;
    const int wm = warp >> 2, wn = warp & 3;
    const int mBase = blockIdx.y * BM, nBase = blockIdx.x * BN;
    const int KT = K / BKH;

    float c[4][8][4];
    #pragma unroll
    for (int i = 0; i < 4; ++i)
        #pragma unroll
        for (int j = 0; j < 8; ++j)
            #pragma unroll
            for (int q = 0; q < 4; ++q) c[i][j][q] = 0.f;

    auto load_tile = [&](int kt, int st) {
        __nv_bfloat16* dst = sm + (size_t)st * STG_ELEMS;
        int k0 = kt * BKH;
        #pragma unroll
        for (int i = 0; i < 12; ++i) {
            int lin = tid + i * 256;
            int r = lin >> 3, cc = (lin & 7) << 3;
            const __nv_bfloat16* src = (r < BM)
                ? Ag + (size_t)(mBase + r) * lda + k0 + cc
                : Bg + (size_t)(nBase + r - BM) * ldb + k0 + cc;
            cp_async16(dst + r * LDSH + cc, src);
        }
        cp_commit();
    };

    load_tile(0, 0);
    load_tile(1, 1);

    for (int kt = 0; kt < KT; ++kt) {
        cp_wait_group<1>();
        __syncthreads();
        int st = kt % NSTG;
        if (kt + 2 < KT) load_tile(kt + 2, (kt + 2) % NSTG);
        else cp_commit();
        const __nv_bfloat16* As = sm + (size_t)st * STG_ELEMS;
        const __nv_bfloat16* Bs = As + BM * LDSH;

        #pragma unroll
        for (int k16 = 0; k16 < 4; ++k16) {
            uint32_t af[4][4];
            #pragma unroll
            for (int mi = 0; mi < 4; ++mi) {
                int row = wm * 64 + mi * 16 + (lane & 15);
                int col = k16 * 16 + ((lane >> 4) << 3);
                uint32_t addr = (uint32_t)__cvta_generic_to_shared(&As[row * LDSH + col]);
                asm volatile("ldmatrix.sync.aligned.m8n8.x4.shared.b16 {%0,%1,%2,%3}, [%4];"
                             : "=r"(af[mi][0]), "=r"(af[mi][1]), "=r"(af[mi][2]), "=r"(af[mi][3])
                             : "r"(addr));
            }
            uint32_t bfr[4][4];
            #pragma unroll
            for (int j = 0; j < 4; ++j) {
                int row = wn * 64 + j * 16 + ((lane >> 4) << 3) + (lane & 7);
                int col = k16 * 16 + (((lane >> 3) & 1) << 3);
                uint32_t addr = (uint32_t)__cvta_generic_to_shared(&Bs[row * LDSH + col]);
                asm volatile("ldmatrix.sync.aligned.m8n8.x4.shared.b16 {%0,%1,%2,%3}, [%4];"
                             : "=r"(bfr[j][0]), "=r"(bfr[j][1]), "=r"(bfr[j][2]), "=r"(bfr[j][3])
                             : "r"(addr));
            }
            #pragma unroll
            for (int mi = 0; mi < 4; ++mi)
                #pragma unroll
                for (int ni = 0; ni < 8; ++ni) {
                    uint32_t b0 = bfr[ni >> 1][(ni & 1) * 2];
                    uint32_t b1 = bfr[ni >> 1][(ni & 1) * 2 + 1];
                    asm volatile("mma.sync.aligned.m16n8k16.row.col.f32.bf16.bf16.f32 "
                                 "{%0,%1,%2,%3}, {%4,%5,%6,%7}, {%8,%9}, {%0,%1,%2,%3};"
                                 : "+f"(c[mi][ni][0]), "+f"(c[mi][ni][1]),
                                   "+f"(c[mi][ni][2]), "+f"(c[mi][ni][3])
                                 : "r"(af[mi][0]), "r"(af[mi][1]), "r"(af[mi][2]), "r"(af[mi][3]),
                                   "r"(b0), "r"(b1));
                }
        }
        __syncthreads();
    }

    const int g = lane >> 2, t = lane & 3;
    #pragma unroll
    for (int mi = 0; mi < 4; ++mi)
        #pragma unroll
        for (int ni = 0; ni < 8; ++ni) {
            int col = nBase + wn * 64 + ni * 8 + t * 2;
            #pragma unroll
            for (int half = 0; half < 2; ++half) {
                int m = mBase + wm * 64 + mi * 16 + g + half * 8;
                __nv_bfloat162 p;
                p.x = __float2bfloat16(c[mi][ni][half * 2 + 0]);
                p.y = __float2bfloat16(c[mi][ni][half * 2 + 1]);
                *reinterpret_cast<__nv_bfloat162*>(out0 + (size_t)m * ldc + col) = p;
            }
        }
}

// ==================== fp8 e4m3 GEMM, 128x256xBK128, 3-stage ====================
// C = A8 @ B8^T * inv + bias.   Same smem footprint as bf16 version.
// MODE 1: sigmoid -> gate bf16 if col<kDI else raw -> val bf16
// MODE 3: outF = resid + acc*inv + bias (fp32)
// MODE 4: y28 = fp8( (acc*inv + bias + aux)*gate * SY2 )
constexpr int BK8 = 128;                       // fp8 elems per k-tile (128 B/row)
constexpr int ROWB = 144;                      // 128 + 16 pad bytes
constexpr int STG_B = NROWS * ROWB;            // 55296
static_assert((size_t)NSTG * STG_B == SMEM_G, "smem mismatch");

template<int MODE>
__global__ __launch_bounds__(256, 1)
void gemm_fp8(const uint8_t* __restrict__ Ag, const uint8_t* __restrict__ Bg,
              const float* __restrict__ bias, float inv,
              int K, int lda, int ldb,
              __nv_bfloat16* __restrict__ outb0, __nv_bfloat16* __restrict__ outb1,
              uint8_t* __restrict__ out8,
              const __nv_bfloat16* __restrict__ gate, const __nv_bfloat16* __restrict__ aux,
              const float* __restrict__ resid, float* __restrict__ outF, int ldc) {
    extern __shared__ __align__(16) uint8_t sm8[];
    const int tid = threadIdx.x, lane = tid & 31, warp = tid >> 5;
    const int wm = warp >> 2, wn = warp & 3;
    const int mBase = blockIdx.y * BM, nBase = blockIdx.x * BN;
    const int KT = K / BK8;

    float c[4][8][4];
    #pragma unroll
    for (int i = 0; i < 4; ++i)
        #pragma unroll
        for (int j = 0; j < 8; ++j)
            #pragma unroll
            for (int q = 0; q < 4; ++q) c[i][j][q] = 0.f;

    auto load_tile = [&](int kt, int st) {
        uint8_t* dst = sm8 + (size_t)st * STG_B;
        int k0 = kt * BK8;
        #pragma unroll
        for (int i = 0; i < 12; ++i) {
            int lin = tid + i * 256;               // 0..3071
            int r = lin >> 3, cc = (lin & 7) << 4; // 8 chunks x 16 B
            const uint8_t* src = (r < BM)
                ? Ag + (size_t)(mBase + r) * lda + k0 + cc
                : Bg + (size_t)(nBase + r - BM) * ldb + k0 + cc;
            cp_async16(dst + r * ROWB + cc, src);
        }
        cp_commit();
    };

    load_tile(0, 0);
    load_tile(1, 1);

    for (int kt = 0; kt < KT; ++kt) {
        cp_wait_group<1>();
        __syncthreads();
        int st = kt % NSTG;
        if (kt + 2 < KT) load_tile(kt + 2, (kt + 2) % NSTG);
        else cp_commit();
        const uint8_t* As = sm8 + (size_t)st * STG_B;
        const uint8_t* Bs = As + BM * ROWB;

        #pragma unroll
        for (int q = 0; q < 4; ++q) {              // 4 x k32 = 128 k
            uint32_t af[4][4];
            #pragma unroll
            for (int mi = 0; mi < 4; ++mi) {
                int row = wm * 64 + mi * 16 + (lane & 15);
                int colB = (q * 16 + ((lane >> 4) << 3)) * 2;      // b16 units -> bytes
                uint32_t addr = (uint32_t)__cvta_generic_to_shared(As + row * ROWB + colB);
                asm volatile("ldmatrix.sync.aligned.m8n8.x4.shared.b16 {%0,%1,%2,%3}, [%4];"
                             : "=r"(af[mi][0]), "=r"(af[mi][1]), "=r"(af[mi][2]), "=r"(af[mi][3])
                             : "r"(addr));
            }
            uint32_t bfr[4][4];
            #pragma unroll
            for (int j = 0; j < 4; ++j) {
                int row = wn * 64 + j * 16 + ((lane >> 4) << 3) + (lane & 7);
                int colB = (q * 16 + (((lane >> 3) & 1) << 3)) * 2;
                uint32_t addr = (uint32_t)__cvta_generic_to_shared(Bs + row * ROWB + colB);
                asm volatile("ldmatrix.sync.aligned.m8n8.x4.shared.b16 {%0,%1,%2,%3}, [%4];"
                             : "=r"(bfr[j][0]), "=r"(bfr[j][1]), "=r"(bfr[j][2]), "=r"(bfr[j][3])
                             : "r"(addr));
            }
            #pragma unroll
            for (int mi = 0; mi < 4; ++mi)
                #pragma unroll
                for (int ni = 0; ni < 8; ++ni) {
                    uint32_t b0 = bfr[ni >> 1][(ni & 1) * 2];
                    uint32_t b1 = bfr[ni >> 1][(ni & 1) * 2 + 1];
                    asm volatile("mma.sync.aligned.m16n8k32.row.col.f32.e4m3.e4m3.f32 "
                                 "{%0,%1,%2,%3}, {%4,%5,%6,%7}, {%8,%9}, {%0,%1,%2,%3};"
                                 : "+f"(c[mi][ni][0]), "+f"(c[mi][ni][1]),
                                   "+f"(c[mi][ni][2]), "+f"(c[mi][ni][3])
                                 : "r"(af[mi][0]), "r"(af[mi][1]), "r"(af[mi][2]), "r"(af[mi][3]),
                                   "r"(b0), "r"(b1));
                }
        }
        __syncthreads();
    }

    // -------- epilogue --------
    const int g = lane >> 2, t = lane & 3;
    #pragma unroll
    for (int mi = 0; mi < 4; ++mi) {
        #pragma unroll
        for (int ni = 0; ni < 8; ++ni) {
            int col = nBase + wn * 64 + ni * 8 + t * 2;
            #pragma unroll
            for (int half = 0; half < 2; ++half) {
                int m = mBase + wm * 64 + mi * 16 + g + half * 8;
                float v0 = c[mi][ni][half * 2 + 0] * inv + bias[col];
                float v1 = c[mi][ni][half * 2 + 1] * inv + bias[col + 1];
                if (MODE == 1) {
                    if (col < kDI) {
                        __nv_bfloat162 p;
                        p.x = __float2bfloat16(1.f / (1.f + __expf(-v0)));
                        p.y = __float2bfloat16(1.f / (1.f + __expf(-v1)));
                        *reinterpret_cast<__nv_bfloat162*>(outb0 + (size_t)m * kDI + col) = p;
                    } else {
                        __nv_bfloat162 p;
                        p.x = __float2bfloat16(v0); p.y = __float2bfloat16(v1);
                        *reinterpret_cast<__nv_bfloat162*>(outb1 + (size_t)m * kDI + col - kDI) = p;
                    }
                } else if (MODE == 4) {
                    __nv_bfloat162 gp = *reinterpret_cast<const __nv_bfloat162*>(
                        gate + (size_t)m * kDI + col);
                    __nv_bfloat162 ap = *reinterpret_cast<const __nv_bfloat162*>(
                        aux + (size_t)m * kDI + col);
                    float2 fg = __bfloat1622float2(gp);
                    float2 fa = __bfloat1622float2(ap);
                    float y0 = (v0 + fa.x) * fg.x * SY2;
                    float y1 = (v1 + fa.y) * fg.y * SY2;
                    uint16_t pk = (uint16_t)f2e4m3(y0) | ((uint16_t)f2e4m3(y1) << 8);
                    *reinterpret_cast<uint16_t*>(out8 + (size_t)m * kDI + col) = pk;
                } else {  // MODE 3
                    const float2 r = *reinterpret_cast<const float2*>(resid + (size_t)m * ldc + col);
                    float2 o; o.x = r.x + v0; o.y = r.y + v1;
                    *reinterpret_cast<float2*>(outF + (size_t)m * ldc + col) = o;
                }
            }
        }
    }
}

// ==================== host ====================
extern "C" void kernel_launch(void* const* d_in, const int* in_sizes, int n_in,
                              void* d_out, int out_size) {
    const float* x      = (const float*)d_in[0];
    const float* norm_w = (const float*)d_in[1];
    const float* in_w   = (const float*)d_in[2];
    const float* in_b   = (const float*)d_in[3];
    const float* dwa_k  = (const float*)d_in[4];
    const float* dwa_b  = (const float*)d_in[5];
    const float* Amat   = (const float*)d_in[6];
    const float* Bm     = (const float*)d_in[7];
    const float* sym_k  = (const float*)d_in[8];
    const float* sym_b  = (const float*)d_in[9];
    const float* pw_w   = (const float*)d_in[10];
    const float* pw_b   = (const float*)d_in[11];
    const float* ha_w   = (const float*)d_in[12];
    const float* ha_b   = (const float*)d_in[13];
    const float* hb_w   = (const float*)d_in[14];
    const float* hb_b   = (const float*)d_in[15];
    const float* fuse_w = (const float*)d_in[16];
    const float* fuse_b = (const float*)d_in[17];
    const float* out_w  = (const float*)d_in[18];
    const float* out_b  = (const float*)d_in[19];
    float* out = (float*)d_out;

    uint8_t *hn8, *b18, *y28, *w_in8, *w_out8, *W38;
    __nv_bfloat16 *gateB, *valB, *a1, *az, *w_fuse, *hbT, *pwT, *W2, *W3;
    float *a2, *C1, *C2, *zb, *zero_b;
    cudaGetSymbolAddress((void**)&hn8,   g_hn8);
    cudaGetSymbolAddress((void**)&gateB, g_gate);
    cudaGetSymbolAddress((void**)&valB,  g_val);
    cudaGetSymbolAddress((void**)&a1,    g_a1);
    cudaGetSymbolAddress((void**)&a2,    g_a2);
    cudaGetSymbolAddress((void**)&C1,    g_C1);
    cudaGetSymbolAddress((void**)&C2,    g_C2);
    cudaGetSymbolAddress((void**)&b18,   g_b18);
    cudaGetSymbolAddress((void**)&az,    g_az);
    cudaGetSymbolAddress((void**)&y28,   g_y28);
    cudaGetSymbolAddress((void**)&w_in8,  g_w_in8);
    cudaGetSymbolAddress((void**)&w_out8, g_w_out8);
    cudaGetSymbolAddress((void**)&W38,    g_W38);
    cudaGetSymbolAddress((void**)&w_fuse, g_w_fuse);
    cudaGetSymbolAddress((void**)&hbT,    g_hbT);
    cudaGetSymbolAddress((void**)&pwT,    g_pwT);
    cudaGetSymbolAddress((void**)&W2,     g_W2);
    cudaGetSymbolAddress((void**)&W3,     g_W3);
    cudaGetSymbolAddress((void**)&zb,     g_zb);
    cudaGetSymbolAddress((void**)&zero_b, g_zero_bias);

    cudaFuncSetAttribute(gemm_bf16_pre, cudaFuncAttributeMaxDynamicSharedMemorySize, (int)SMEM_G);
    cudaFuncSetAttribute(gemm_fp8<1>, cudaFuncAttributeMaxDynamicSharedMemorySize, (int)SMEM_G);
    cudaFuncSetAttribute(gemm_fp8<3>, cudaFuncAttributeMaxDynamicSharedMemorySize, (int)SMEM_G);
    cudaFuncSetAttribute(gemm_fp8<4>, cudaFuncAttributeMaxDynamicSharedMemorySize, (int)SMEM_G);

    // weight conversions + transposes
    f2f8_kernel<<<1024, 256>>>((const float4*)in_w,  (uint32_t*)w_in8,  (2*kDI*kD)/4, SW);
    f2f8_kernel<<<512,  256>>>((const float4*)out_w, (uint32_t*)w_out8, (kD*kDI)/4,  SW);
    f2bf_kernel<<<1024, 256>>>((const float4*)fuse_w, (uint2*)w_fuse, (kDI*kDI)/4);
    transpose_f2bf<<<dim3(kDI/32, kD/32),  dim3(32,8)>>>(hb_w, hbT, kD,  kDI);
    transpose_f2bf<<<dim3(kDI/32, kDI/32), dim3(32,8)>>>(pw_w, pwT, kDI, kDI);

    // W2 = F2 @ hb_w ; W3 = W2 @ pw_w  (bf16 precompute)
    gemm_bf16_pre<<<dim3(kDI/BN, kDI/BM), 256, SMEM_G>>>(
        w_fuse + kD, hbT, kD, kDI, kD, W2, kDI);
    gemm_bf16_pre<<<dim3(kDI/BN, kDI/BM), 256, SMEM_G>>>(
        W2, pwT, kDI, kDI, kDI, W3, kDI);
    bf2f8_kernel<<<1024, 256>>>(W3, (uint32_t*)W38, (kDI*kDI)/4, SW);

    // folded bias
    zbias_kernel<<<(kDI*32)/256, 256>>>(fuse_b, ha_b, hb_b, pw_b, fuse_w, W2, zb);

    rmsnorm_kernel<<<kM, 256>>>(x, norm_w, hn8);

    // in-proj (fp8): sigmoid(gate)/val split
    gemm_fp8<1><<<dim3((2*kDI)/BN, kM/BM), 256, SMEM_G>>>(
        hn8, w_in8, in_b, INV_IN, kD, kD, kD,
        gateB, valB, nullptr, nullptr, nullptr, nullptr, nullptr, kDI);

    // fused depthwise convs
    dwconv_fused_kernel<<<(kM*kDI)/256, 256>>>(valB, dwa_k, dwa_b, sym_k, sym_b, a1, b18);

    // low-rank a-path
    lowrank_a2_kernel<<<(kM*32)/256, 256>>>(a1, Amat, a2);
    c1_kernel<<<(kDS*kD*32)/256, 256>>>(Bm, ha_w, C1);
    c2_kernel<<<(kDS*kDI*32)/256, 256>>>(C1, fuse_w, C2);
    aadd_kernel<<<(kM*kDI)/256, 256>>>(a2, C2, az);

    // fuse (fp8): y28 = fp8( gate * (b1 @ W3^T + az + zb) * SY2 )
    gemm_fp8<4><<<dim3(kDI/BN, kM/BM), 256, SMEM_G>>>(
        b18, W38, zb, INV_FUSE, kDI, kDI, kDI,
        nullptr, nullptr, y28, gateB, az, nullptr, nullptr, kDI);

    // out-proj (fp8) with residual add, fp32 out
    gemm_fp8<3><<<dim3(kD/BN, kM/BM), 256, SMEM_G>>>(
        y28, w_out8, out_b, INV_OUT, kDI, kDI, kDI,
        nullptr, nullptr, nullptr, nullptr, nullptr, x, out, kD);
}

// round 13
// speedup vs baseline: 1.0687x; 1.0687x over previous
#include <cuda_runtime.h>
#include <cuda_bf16.h>
#include <cstdint>

constexpr int kL  = 4096;
constexpr int kD  = 1024;
constexpr int kDI = 2048;
constexpr int kM  = 4 * kL;           // 16384
constexpr int kDS = 16;
constexpr int kKE = kDI + 64;         // 2112: K-extended (b1 | a2 | zeros)

// ---------------- static scratch (zero-initialized; pad columns never written) ----
__device__ __align__(256) __nv_bfloat16 g_hn   [(size_t)kM * kD];
__device__ __align__(256) __nv_bfloat16 g_gate [(size_t)kM * kDI];
__device__ __align__(256) __nv_bfloat16 g_val  [(size_t)kM * kDI];
__device__ __align__(256) __nv_bfloat16 g_a1   [(size_t)kM * kDI];
__device__ __align__(256) __nv_bfloat16 g_b1e  [(size_t)kM * kKE];     // [b1 | a2 | 0]
__device__ __align__(256) __nv_bfloat16 g_y2   [(size_t)kM * kDI];
__device__ __align__(256) __nv_bfloat16 g_w_in [(size_t)2*kDI * kD];
__device__ __align__(256) __nv_bfloat16 g_w_fuse[(size_t)kDI * kDI];
__device__ __align__(256) __nv_bfloat16 g_w_out[(size_t)kD * kDI];
__device__ __align__(256) __nv_bfloat16 g_hb_bf[(size_t)kD * kDI];
__device__ __align__(256) __nv_bfloat16 g_pwT  [(size_t)kDI * kDI];
__device__ __align__(256) __nv_bfloat16 g_U    [(size_t)kDI * kD];     // (hb_w@pw_w)^T [2048,1024]
__device__ __align__(256) __nv_bfloat16 g_W3e  [(size_t)kDI * kKE];    // [W3 | C2^T | 0]
__device__ __align__(256) float         g_C1   [(size_t)kDS * kD];
__device__ float g_u [kD];
__device__ float g_zb[kDI];

#define DEVFN __device__ __forceinline__

DEVFN void cp_async16(void* smem, const void* gmem) {
    uint32_t a = (uint32_t)__cvta_generic_to_shared(smem);
    asm volatile("cp.async.cg.shared.global [%0], [%1], 16;" :: "r"(a), "l"(gmem));
}
DEVFN void cp_commit() { asm volatile("cp.async.commit_group;"); }
template<int N> DEVFN void cp_wait_group() { asm volatile("cp.async.wait_group %0;" :: "n"(N)); }

// ---------------- conversion / elementwise kernels ----------------
__global__ void f2bf_kernel(const float4* __restrict__ s, uint2* __restrict__ d, int n4) {
    int i = blockIdx.x * blockDim.x + threadIdx.x, st = gridDim.x * blockDim.x;
    for (; i < n4; i += st) {
        float4 v = s[i];
        __nv_bfloat162 lo = __floats2bfloat162_rn(v.x, v.y);
        __nv_bfloat162 hi = __floats2bfloat162_rn(v.z, v.w);
        uint2 o; o.x = *(uint32_t*)&lo; o.y = *(uint32_t*)&hi;
        d[i] = o;
    }
}

// transpose fp32 [R,C] -> bf16 [C,R]
__global__ void transpose_f2bf(const float* __restrict__ src, __nv_bfloat16* __restrict__ dst,
                               int R, int C) {
    __shared__ float t[32][33];
    int c0 = blockIdx.x * 32, r0 = blockIdx.y * 32;
    int x = threadIdx.x;
    #pragma unroll
    for (int y = threadIdx.y; y < 32; y += 8)
        t[y][x] = src[(size_t)(r0 + y) * C + c0 + x];
    __syncthreads();
    #pragma unroll
    for (int y = threadIdx.y; y < 32; y += 8)
        dst[(size_t)(c0 + y) * R + r0 + x] = __float2bfloat16(t[x][y]);
}

__global__ void rmsnorm_kernel(const float* __restrict__ x, const float* __restrict__ w,
                               __nv_bfloat16* __restrict__ out) {
    int m = blockIdx.x;
    const float* xr = x + (size_t)m * kD;
    float ss = 0.f;
    for (int c = threadIdx.x; c < kD; c += 256) { float v = xr[c]; ss += v * v; }
    #pragma unroll
    for (int o = 16; o; o >>= 1) ss += __shfl_xor_sync(~0u, ss, o);
    __shared__ float red[8];
    if ((threadIdx.x & 31) == 0) red[threadIdx.x >> 5] = ss;
    __syncthreads();
    float tot = 0.f;
    #pragma unroll
    for (int i = 0; i < 8; ++i) tot += red[i];
    float sc = rsqrtf(tot * (1.f / kD) + 1e-6f);
    for (int c = threadIdx.x; c < kD; c += 256)
        out[(size_t)m * kD + c] = __float2bfloat16(w[c] * xr[c] * sc);
}

// fused depthwise convs: a1 = conv4(val) (bf16 buf), b1 -> b1e cols [0,2048)
__global__ void dwconv_fused_kernel(const __nv_bfloat16* __restrict__ val,
                                    const float* __restrict__ k4, const float* __restrict__ b4,
                                    const float* __restrict__ k9, const float* __restrict__ b9,
                                    __nv_bfloat16* __restrict__ a1, __nv_bfloat16* __restrict__ b1e) {
    int idx = blockIdx.x * blockDim.x + threadIdx.x;
    int c = idx & (kDI - 1);
    int m = idx >> 11;
    int l = m & (kL - 1);
    float v[9];
    #pragma unroll
    for (int t = 0; t < 9; ++t) {
        int ll = l + t - 4;
        v[t] = (ll >= 0 && ll < kL) ? __bfloat162float(val[(size_t)(m + t - 4) * kDI + c]) : 0.f;
    }
    float a = b4[c];
    #pragma unroll
    for (int t = 0; t < 4; ++t) a += v[t + 3] * k4[c * 4 + t];
    float b = b9[c];
    #pragma unroll
    for (int t = 0; t < 9; ++t) b += v[t] * k9[c * 9 + t];
    a1[idx] = __float2bfloat16(a);
    b1e[(size_t)m * kKE + c] = __float2bfloat16(b / (1.f + __expf(-b)));
}

// a2 row -> bf16 into b1e cols [2048, 2064)
__global__ void lowrank_a2_kernel(const __nv_bfloat16* __restrict__ a1,
                                  const float* __restrict__ A, __nv_bfloat16* __restrict__ b1e) {
    int warp = (blockIdx.x * blockDim.x + threadIdx.x) >> 5;
    int lane = threadIdx.x & 31;
    if (warp >= kM) return;
    float acc[kDS];
    #pragma unroll
    for (int s = 0; s < kDS; ++s) acc[s] = 0.f;
    const __nv_bfloat16* row = a1 + (size_t)warp * kDI;
    for (int c = lane; c < kDI; c += 32) {
        float av = __bfloat162float(row[c]);
        const float* Ac = A + (size_t)c * kDS;
        #pragma unroll
        for (int s = 0; s < kDS; ++s) acc[s] += av * Ac[s];
    }
    #pragma unroll
    for (int s = 0; s < kDS; ++s) {
        #pragma unroll
        for (int o = 16; o; o >>= 1) acc[s] += __shfl_xor_sync(~0u, acc[s], o);
    }
    if (lane == 0) {
        __nv_bfloat16* dst = b1e + (size_t)warp * kKE + kDI;
        #pragma unroll
        for (int s = 0; s < kDS; ++s) dst[s] = __float2bfloat16(acc[s]);
    }
}

// C1[s,h] = sum_d Bm[s,d] * ha_w[h,d]
__global__ void c1_kernel(const float* __restrict__ Bm, const float* __restrict__ ha_w,
                          float* __restrict__ C1) {
    int g = (blockIdx.x * blockDim.x + threadIdx.x) >> 5;
    int lane = threadIdx.x & 31;
    if (g >= kDS * kD) return;
    int s = g >> 10, h = g & 1023;
    float acc = 0.f;
    const float* br = Bm + (size_t)s * kDI;
    const float* hr = ha_w + (size_t)h * kDI;
    for (int d = lane; d < kDI; d += 32) acc += br[d] * hr[d];
    #pragma unroll
    for (int o = 16; o; o >>= 1) acc += __shfl_xor_sync(~0u, acc, o);
    if (lane == 0) C1[(size_t)s * kD + h] = acc;
}

// C2[s,o] = sum_h C1[s,h]*F1[o,h]  ->  W3e[o*kKE + 2048 + s] (bf16)
__global__ void c2_kernel(const float* __restrict__ C1, const float* __restrict__ fuse_w,
                          __nv_bfloat16* __restrict__ W3e) {
    int g = (blockIdx.x * blockDim.x + threadIdx.x) >> 5;
    int lane = threadIdx.x & 31;
    if (g >= kDS * kDI) return;
    int s = g >> 11, o = g & (kDI - 1);
    float acc = 0.f;
    const float* cr = C1 + (size_t)s * kD;
    const float* fr = fuse_w + (size_t)o * kDI;
    for (int h = lane; h < kD; h += 32) acc += cr[h] * fr[h];
    #pragma unroll
    for (int q = 16; q; q >>= 1) acc += __shfl_xor_sync(~0u, acc, q);
    if (lane == 0) W3e[(size_t)o * kKE + kDI + s] = __float2bfloat16(acc);
}

// u[h] = sum_o1 hb_w[h,o1] * pw_b[o1]
__global__ void u_kernel(const float* __restrict__ hb_w, const float* __restrict__ pw_b,
                         float* __restrict__ u) {
    int h = (blockIdx.x * blockDim.x + threadIdx.x) >> 5;
    int lane = threadIdx.x & 31;
    if (h >= kD) return;
    float acc = 0.f;
    const float* hr = hb_w + (size_t)h * kDI;
    for (int o = lane; o < kDI; o += 32) acc += hr[o] * pw_b[o];
    #pragma unroll
    for (int q = 16; q; q >>= 1) acc += __shfl_xor_sync(~0u, acc, q);
    if (lane == 0) u[h] = acc;
}

// zb[o] = fuse_b[o] + sum_h( ha_b[h]*F1[o,h] + (hb_b[h]+u[h])*F2[o,h] )
__global__ void zbias_kernel(const float* __restrict__ fuse_b, const float* __restrict__ ha_b,
                             const float* __restrict__ hb_b, const float* __restrict__ u,
                             const float* __restrict__ fuse_w, float* __restrict__ zb) {
    int o = (blockIdx.x * blockDim.x + threadIdx.x) >> 5;
    int lane = threadIdx.x & 31;
    if (o >= kDI) return;
    float acc = 0.f;
    const float* fr = fuse_w + (size_t)o * kDI;
    for (int h = lane; h < kD; h += 32)
        acc += ha_b[h] * fr[h] + (hb_b[h] + u[h]) * fr[kD + h];
    #pragma unroll
    for (int q = 16; q; q >>= 1) acc += __shfl_xor_sync(~0u, acc, q);
    if (lane == 0) zb[o] = fuse_b[o] + acc;
}

// ==================== bf16 mma.sync GEMM, 128x256x64, 3-stage, 1 sync/iter ========
// C[M,N] = A[M,K] @ B[N,K]^T + bias
// MODE 0: bf16 -> out0[m*ldc + n]  (no bias)
// MODE 1: sigmoid -> out0 if col<kDI else raw -> out1 (col-kDI); ldc=kDI
// MODE 2: bf16 -> out0 = (acc + bias) * gate[m*kDI+col]
// MODE 3: outF = resid + acc + bias (fp32)
constexpr int BM = 128, BN = 256, BK = 64, LDS = BK + 8;
constexpr int NROWS = BM + BN;
constexpr int NSTG  = 3;
constexpr int STG_ELEMS = NROWS * LDS;
constexpr size_t SMEM_G = (size_t)NSTG * STG_ELEMS * 2;     // 165888 B

template<int MODE>
__global__ __launch_bounds__(256, 1)
void gemm_bf16(const __nv_bfloat16* __restrict__ Ag,
               const __nv_bfloat16* __restrict__ Bg,
               const float* __restrict__ bias,
               int K, int lda, int ldb,
               __nv_bfloat16* __restrict__ out0,
               __nv_bfloat16* __restrict__ out1,
               const __nv_bfloat16* __restrict__ gate,
               const float* __restrict__ resid,
               float* __restrict__ outF,
               int ldc) {
    extern __shared__ __align__(16) __nv_bfloat16 sm[];
    const int tid  = threadIdx.x;
    const int lane = tid & 31;
    const int warp = tid >> 5;
    const int wm = warp >> 2, wn = warp & 3;
    const int mBase = blockIdx.y * BM;
    const int nBase = blockIdx.x * BN;
    const int KT = K / BK;

    float c[4][8][4];
    #pragma unroll
    for (int i = 0; i < 4; ++i)
        #pragma unroll
        for (int j = 0; j < 8; ++j)
            #pragma unroll
            for (int q = 0; q < 4; ++q) c[i][j][q] = 0.f;

    auto load_tile = [&](int kt, int st) {
        __nv_bfloat16* dst = sm + (size_t)st * STG_ELEMS;
        int k0 = kt * BK;
        #pragma unroll
        for (int i = 0; i < 12; ++i) {
            int lin = tid + i * 256;
            int r = lin >> 3, cc = (lin & 7) << 3;
            const __nv_bfloat16* src = (r < BM)
                ? Ag + (size_t)(mBase + r) * lda + k0 + cc
                : Bg + (size_t)(nBase + r - BM) * ldb + k0 + cc;
            cp_async16(dst + r * LDS + cc, src);
        }
        cp_commit();
    };

    load_tile(0, 0);
    load_tile(1, 1);

    for (int kt = 0; kt < KT; ++kt) {
        cp_wait_group<1>();
        __syncthreads();                       // single barrier per iteration
        int st = kt % NSTG;
        if (kt + 2 < KT) load_tile(kt + 2, (kt + 2) % NSTG);
        else cp_commit();
        const __nv_bfloat16* As = sm + (size_t)st * STG_ELEMS;
        const __nv_bfloat16* Bs = As + BM * LDS;

        #pragma unroll
        for (int k16 = 0; k16 < 4; ++k16) {
            uint32_t af[4][4];
            #pragma unroll
            for (int mi = 0; mi < 4; ++mi) {
                int row = wm * 64 + mi * 16 + (lane & 15);
                int col = k16 * 16 + ((lane >> 4) << 3);
                uint32_t addr = (uint32_t)__cvta_generic_to_shared(&As[row * LDS + col]);
                asm volatile("ldmatrix.sync.aligned.m8n8.x4.shared.b16 {%0,%1,%2,%3}, [%4];"
                             : "=r"(af[mi][0]), "=r"(af[mi][1]), "=r"(af[mi][2]), "=r"(af[mi][3])
                             : "r"(addr));
            }
            uint32_t bfr[4][4];
            #pragma unroll
            for (int j = 0; j < 4; ++j) {
                int row = wn * 64 + j * 16 + ((lane >> 4) << 3) + (lane & 7);
                int col = k16 * 16 + (((lane >> 3) & 1) << 3);
                uint32_t addr = (uint32_t)__cvta_generic_to_shared(&Bs[row * LDS + col]);
                asm volatile("ldmatrix.sync.aligned.m8n8.x4.shared.b16 {%0,%1,%2,%3}, [%4];"
                             : "=r"(bfr[j][0]), "=r"(bfr[j][1]), "=r"(bfr[j][2]), "=r"(bfr[j][3])
                             : "r"(addr));
            }
            #pragma unroll
            for (int mi = 0; mi < 4; ++mi)
                #pragma unroll
                for (int ni = 0; ni < 8; ++ni) {
                    uint32_t b0 = bfr[ni >> 1][(ni & 1) * 2];
                    uint32_t b1 = bfr[ni >> 1][(ni & 1) * 2 + 1];
                    asm volatile("mma.sync.aligned.m16n8k16.row.col.f32.bf16.bf16.f32 "
                                 "{%0,%1,%2,%3}, {%4,%5,%6,%7}, {%8,%9}, {%0,%1,%2,%3};"
                                 : "+f"(c[mi][ni][0]), "+f"(c[mi][ni][1]),
                                   "+f"(c[mi][ni][2]), "+f"(c[mi][ni][3])
                                 : "r"(af[mi][0]), "r"(af[mi][1]), "r"(af[mi][2]), "r"(af[mi][3]),
                                   "r"(b0), "r"(b1));
                }
        }
    }

    // -------- epilogue --------
    const int g = lane >> 2, t = lane & 3;
    #pragma unroll
    for (int mi = 0; mi < 4; ++mi) {
        #pragma unroll
        for (int ni = 0; ni < 8; ++ni) {
            int col = nBase + wn * 64 + ni * 8 + t * 2;
            #pragma unroll
            for (int half = 0; half < 2; ++half) {
                int m = mBase + wm * 64 + mi * 16 + g + half * 8;
                float b0 = (MODE == 0) ? 0.f : bias[col];
                float b1v = (MODE == 0) ? 0.f : bias[col + 1];
                float v0 = c[mi][ni][half * 2 + 0] + b0;
                float v1 = c[mi][ni][half * 2 + 1] + b1v;
                if (MODE == 0) {
                    __nv_bfloat162 p;
                    p.x = __float2bfloat16(v0); p.y = __float2bfloat16(v1);
                    *reinterpret_cast<__nv_bfloat162*>(out0 + (size_t)m * ldc + col) = p;
                } else if (MODE == 1) {
                    if (col < kDI) {
                        __nv_bfloat162 p;
                        p.x = __float2bfloat16(1.f / (1.f + __expf(-v0)));
                        p.y = __float2bfloat16(1.f / (1.f + __expf(-v1)));
                        *reinterpret_cast<__nv_bfloat162*>(out0 + (size_t)m * kDI + col) = p;
                    } else {
                        __nv_bfloat162 p;
                        p.x = __float2bfloat16(v0); p.y = __float2bfloat16(v1);
                        *reinterpret_cast<__nv_bfloat162*>(out1 + (size_t)m * kDI + col - kDI) = p;
                    }
                } else if (MODE == 2) {
                    __nv_bfloat162 gp = *reinterpret_cast<const __nv_bfloat162*>(
                        gate + (size_t)m * kDI + col);
                    float2 fg = __bfloat1622float2(gp);
                    __nv_bfloat162 p;
                    p.x = __float2bfloat16(v0 * fg.x);
                    p.y = __float2bfloat16(v1 * fg.y);
                    *reinterpret_cast<__nv_bfloat162*>(out0 + (size_t)m * kDI + col) = p;
                } else {
                    const float2 r = *reinterpret_cast<const float2*>(resid + (size_t)m * ldc + col);
                    float2 o; o.x = r.x + v0; o.y = r.y + v1;
                    *reinterpret_cast<float2*>(outF + (size_t)m * ldc + col) = o;
                }
            }
        }
    }
}

// ==================== host ====================
extern "C" void kernel_launch(void* const* d_in, const int* in_sizes, int n_in,
                              void* d_out, int out_size) {
    const float* x      = (const float*)d_in[0];
    const float* norm_w = (const float*)d_in[1];
    const float* in_w   = (const float*)d_in[2];
    const float* in_b   = (const float*)d_in[3];
    const float* dwa_k  = (const float*)d_in[4];
    const float* dwa_b  = (const float*)d_in[5];
    const float* Amat   = (const float*)d_in[6];
    const float* Bm     = (const float*)d_in[7];
    const float* sym_k  = (const float*)d_in[8];
    const float* sym_b  = (const float*)d_in[9];
    const float* pw_w   = (const float*)d_in[10];
    const float* pw_b   = (const float*)d_in[11];
    const float* ha_w   = (const float*)d_in[12];
    const float* ha_b   = (const float*)d_in[13];
    const float* hb_w   = (const float*)d_in[14];
    const float* hb_b   = (const float*)d_in[15];
    const float* fuse_w = (const float*)d_in[16];
    const float* fuse_b = (const float*)d_in[17];
    const float* out_w  = (const float*)d_in[18];
    const float* out_b  = (const float*)d_in[19];
    float* out = (float*)d_out;

    __nv_bfloat16 *hn, *gateB, *valB, *a1, *b1e, *y2;
    __nv_bfloat16 *w_in, *w_fuse, *w_out, *hb_bf, *pwT, *U, *W3e;
    float *C1, *uvec, *zb;
    cudaGetSymbolAddress((void**)&hn,    g_hn);
    cudaGetSymbolAddress((void**)&gateB, g_gate);
    cudaGetSymbolAddress((void**)&valB,  g_val);
    cudaGetSymbolAddress((void**)&a1,    g_a1);
    cudaGetSymbolAddress((void**)&b1e,   g_b1e);
    cudaGetSymbolAddress((void**)&y2,    g_y2);
    cudaGetSymbolAddress((void**)&w_in,   g_w_in);
    cudaGetSymbolAddress((void**)&w_fuse, g_w_fuse);
    cudaGetSymbolAddress((void**)&w_out,  g_w_out);
    cudaGetSymbolAddress((void**)&hb_bf,  g_hb_bf);
    cudaGetSymbolAddress((void**)&pwT,    g_pwT);
    cudaGetSymbolAddress((void**)&U,      g_U);
    cudaGetSymbolAddress((void**)&W3e,    g_W3e);
    cudaGetSymbolAddress((void**)&C1,     g_C1);
    cudaGetSymbolAddress((void**)&uvec,   g_u);
    cudaGetSymbolAddress((void**)&zb,     g_zb);

    cudaFuncSetAttribute(gemm_bf16<0>, cudaFuncAttributeMaxDynamicSharedMemorySize, (int)SMEM_G);
    cudaFuncSetAttribute(gemm_bf16<1>, cudaFuncAttributeMaxDynamicSharedMemorySize, (int)SMEM_G);
    cudaFuncSetAttribute(gemm_bf16<2>, cudaFuncAttributeMaxDynamicSharedMemorySize, (int)SMEM_G);
    cudaFuncSetAttribute(gemm_bf16<3>, cudaFuncAttributeMaxDynamicSharedMemorySize, (int)SMEM_G);

    // 0-3: rmsnorm + conversions needed by in-GEMM
    rmsnorm_kernel<<<kM, 256>>>(x, norm_w, hn);
    f2bf_kernel<<<1024, 256>>>((const float4*)in_w,   (uint2*)w_in,   (2*kDI*kD)/4);
    f2bf_kernel<<<1024, 256>>>((const float4*)fuse_w, (uint2*)w_fuse, (kDI*kDI)/4);
    f2bf_kernel<<<512,  256>>>((const float4*)out_w,  (uint2*)w_out,  (kD*kDI)/4);

    // 4: in-proj GEMM (ncu capture target)
    gemm_bf16<1><<<dim3((2*kDI)/BN, kM/BM), 256, SMEM_G>>>(
        hn, w_in, in_b, kD, kD, kD, gateB, valB, nullptr, nullptr, nullptr, kDI);

    // 5: fused depthwise convs (b1 -> b1e cols 0..2047, a1 buffer)
    dwconv_fused_kernel<<<(kM*kDI)/256, 256>>>(valB, dwa_k, dwa_b, sym_k, sym_b, a1, b1e);

    // 6: a2 -> b1e cols 2048..2063
    lowrank_a2_kernel<<<(kM*32)/256, 256>>>(a1, Amat, b1e);

    // precompute chain for W3e
    f2bf_kernel<<<512, 256>>>((const float4*)hb_w, (uint2*)hb_bf, (kD*kDI)/4);
    transpose_f2bf<<<dim3(kDI/32, kDI/32), dim3(32,8)>>>(pw_w, pwT, kDI, kDI);
    // U = pwT @ hb_bf^T : [2048,1024]
    gemm_bf16<0><<<dim3(kD/BN, kDI/BM), 256, SMEM_G>>>(
        pwT, hb_bf, nullptr, kDI, kDI, kDI, U, nullptr, nullptr, nullptr, nullptr, kD);
    // W3e[:, :2048] = F2 @ U^T : [2048,2048], ldc = kKE
    gemm_bf16<0><<<dim3(kDI/BN, kDI/BM), 256, SMEM_G>>>(
        w_fuse + kD, U, nullptr, kD, kDI, kD, W3e, nullptr, nullptr, nullptr, nullptr, kKE);
    // bias folding
    u_kernel<<<(kD*32)/256, 256>>>(hb_w, pw_b, uvec);
    zbias_kernel<<<(kDI*32)/256, 256>>>(fuse_b, ha_b, hb_b, uvec, fuse_w, zb);
    // a-path rank-16 factors -> W3e cols 2048..2063
    c1_kernel<<<(kDS*kD*32)/256, 256>>>(Bm, ha_w, C1);
    c2_kernel<<<(kDS*kDI*32)/256, 256>>>(C1, fuse_w, W3e);

    // fuse GEMM (K = 2112, folded a-path + biases), gate-multiply epilogue
    gemm_bf16<2><<<dim3(kDI/BN, kM/BM), 256, SMEM_G>>>(
        b1e, W3e, zb, kKE, kKE, kKE, y2, nullptr, gateB, nullptr, nullptr, kDI);

    // out-proj with residual add, fp32 out
    gemm_bf16<3><<<dim3(kD/BN, kM/BM), 256, SMEM_G>>>(
        y2, w_out, out_b, kDI, kDI, kDI, nullptr, nullptr, nullptr, x, out, kD);
}

// round 15
// speedup vs baseline: 1.4413x; 1.3486x over previous
#include <cuda_runtime.h>
#include <cuda_bf16.h>
#include <cstdint>

constexpr int kL  = 4096;
constexpr int kD  = 1024;
constexpr int kDI = 2048;
constexpr int kM  = 4 * kL;           // 16384
constexpr int kDS = 16;
constexpr int kKE = kDI + 64;         // 2112: K-extended (b1 | a2 | zeros)

// ---------------- static scratch (zero-initialized; pad columns never written) ----
__device__ __align__(256) __nv_bfloat16 g_hn   [(size_t)kM * kD];
__device__ __align__(256) __nv_bfloat16 g_gate [(size_t)kM * kDI];
__device__ __align__(256) __nv_bfloat16 g_val  [(size_t)kM * kDI];
__device__ __align__(256) __nv_bfloat16 g_b1e  [(size_t)kM * kKE];     // [b1 | a2 | 0]
__device__ __align__(256) __nv_bfloat16 g_y2   [(size_t)kM * kDI];
__device__ __align__(256) __nv_bfloat16 g_w_in [(size_t)2*kDI * kD];
__device__ __align__(256) __nv_bfloat16 g_w_fuse[(size_t)kDI * kDI];
__device__ __align__(256) __nv_bfloat16 g_w_out[(size_t)kD * kDI];
__device__ __align__(256) __nv_bfloat16 g_hb_bf[(size_t)kD * kDI];
__device__ __align__(256) __nv_bfloat16 g_pwT  [(size_t)kDI * kDI];
__device__ __align__(256) __nv_bfloat16 g_U    [(size_t)kDI * kD];     // (hb_w@pw_w)^T [2048,1024]
__device__ __align__(256) __nv_bfloat16 g_W3e  [(size_t)kDI * kKE];    // [W3 | C2^T | 0]
__device__ __align__(256) float         g_C1   [(size_t)kDS * kD];
__device__ float g_u [kD];
__device__ float g_zb[kDI];

#define DEVFN __device__ __forceinline__

DEVFN void cp_async16(void* smem, const void* gmem) {
    uint32_t a = (uint32_t)__cvta_generic_to_shared(smem);
    asm volatile("cp.async.cg.shared.global [%0], [%1], 16;" :: "r"(a), "l"(gmem));
}
DEVFN void cp_commit() { asm volatile("cp.async.commit_group;"); }
template<int N> DEVFN void cp_wait_group() { asm volatile("cp.async.wait_group %0;" :: "n"(N)); }

// ---------------- conversion / elementwise kernels ----------------
__global__ void f2bf_kernel(const float4* __restrict__ s, uint2* __restrict__ d, int n4) {
    int i = blockIdx.x * blockDim.x + threadIdx.x, st = gridDim.x * blockDim.x;
    for (; i < n4; i += st) {
        float4 v = s[i];
        __nv_bfloat162 lo = __floats2bfloat162_rn(v.x, v.y);
        __nv_bfloat162 hi = __floats2bfloat162_rn(v.z, v.w);
        uint2 o; o.x = *(uint32_t*)&lo; o.y = *(uint32_t*)&hi;
        d[i] = o;
    }
}

// transpose fp32 [R,C] -> bf16 [C,R]
__global__ void transpose_f2bf(const float* __restrict__ src, __nv_bfloat16* __restrict__ dst,
                               int R, int C) {
    __shared__ float t[32][33];
    int c0 = blockIdx.x * 32, r0 = blockIdx.y * 32;
    int x = threadIdx.x;
    #pragma unroll
    for (int y = threadIdx.y; y < 32; y += 8)
        t[y][x] = src[(size_t)(r0 + y) * C + c0 + x];
    __syncthreads();
    #pragma unroll
    for (int y = threadIdx.y; y < 32; y += 8)
        dst[(size_t)(c0 + y) * R + r0 + x] = __float2bfloat16(t[x][y]);
}

__global__ void rmsnorm_kernel(const float* __restrict__ x, const float* __restrict__ w,
                               __nv_bfloat16* __restrict__ out) {
    int m = blockIdx.x;
    const float* xr = x + (size_t)m * kD;
    float ss = 0.f;
    for (int c = threadIdx.x; c < kD; c += 256) { float v = xr[c]; ss += v * v; }
    #pragma unroll
    for (int o = 16; o; o >>= 1) ss += __shfl_xor_sync(~0u, ss, o);
    __shared__ float red[8];
    if ((threadIdx.x & 31) == 0) red[threadIdx.x >> 5] = ss;
    __syncthreads();
    float tot = 0.f;
    #pragma unroll
    for (int i = 0; i < 8; ++i) tot += red[i];
    float sc = rsqrtf(tot * (1.f / kD) + 1e-6f);
    for (int c = threadIdx.x; c < kD; c += 256)
        out[(size_t)m * kD + c] = __float2bfloat16(w[c] * xr[c] * sc);
}

// ==================== fused dwconv + low-rank a2, SMEM-tiled ====================
// Block = 16 m-rows x 2048 channels. SMEM: val tile (24 rows incl. 4/4 halo, 96KB)
// + abuf (conv4 result, 16x2056 bf16, 64.25KB). Writes:
//   b1e[m, 0..2047]    = silu(conv9(val))
//   b1e[m, 2048..2063] = conv4(val) @ A   (rank-16)
constexpr int TMR   = 16;
constexpr int VROWS = TMR + 8;            // 24
constexpr int APITCH = kDI + 8;           // 2056 (bank-skew pad)
constexpr size_t DSM_DW = (size_t)VROWS * kDI * 2 + (size_t)TMR * APITCH * 2;  // 164096 B

__global__ __launch_bounds__(256, 1)
void dwconv2_kernel(const __nv_bfloat16* __restrict__ val,
                    const float* __restrict__ k4, const float* __restrict__ b4,
                    const float* __restrict__ k9, const float* __restrict__ b9,
                    const float* __restrict__ A,
                    __nv_bfloat16* __restrict__ b1e) {
    extern __shared__ __align__(16) char ds[];
    __nv_bfloat16* vt = reinterpret_cast<__nv_bfloat16*>(ds);                       // [24][2048]
    __nv_bfloat16* ab = reinterpret_cast<__nv_bfloat16*>(ds + (size_t)VROWS * kDI * 2); // [16][2056]
    const int tid = threadIdx.x;
    const int m0 = blockIdx.x * TMR;
    const int l0 = m0 & (kL - 1);

    // ---- load 24 rows (halo zero-filled at batch edges) ----
    #pragma unroll
    for (int vr = 0; vr < VROWS; ++vr) {
        int l = l0 - 4 + vr;
        void* dst = vt + (size_t)vr * kDI + tid * 8;
        if (l >= 0 && l < kL)
            cp_async16(dst, val + (size_t)(m0 - 4 + vr) * kDI + tid * 8);
        else
            *reinterpret_cast<uint4*>(dst) = make_uint4(0, 0, 0, 0);
    }
    cp_commit();
    cp_wait_group<0>();
    __syncthreads();

    // ---- conv: each thread owns 8 channels (c = tid + 256k), sliding window ----
    #pragma unroll 1
    for (int k = 0; k < 8; ++k) {
        int c = tid + k * 256;
        float w4[4], w9[9];
        #pragma unroll
        for (int t = 0; t < 4; ++t) w4[t] = k4[c * 4 + t];
        #pragma unroll
        for (int t = 0; t < 9; ++t) w9[t] = k9[c * 9 + t];
        float bb4 = b4[c], bb9 = b9[c];
        float v[VROWS];
        #pragma unroll
        for (int r = 0; r < VROWS; ++r) v[r] = __bfloat162float(vt[(size_t)r * kDI + c]);
        #pragma unroll
        for (int ro = 0; ro < TMR; ++ro) {
            float a = bb4;
            #pragma unroll
            for (int t = 0; t < 4; ++t) a += v[ro + 3 + t] * w4[t];
            float b = bb9;
            #pragma unroll
            for (int t = 0; t < 9; ++t) b += v[ro + t] * w9[t];
            b1e[(size_t)(m0 + ro) * kKE + c] = __float2bfloat16(b / (1.f + __expf(-b)));
            ab[(size_t)ro * APITCH + c] = __float2bfloat16(a);
        }
    }
    __syncthreads();

    // ---- a2: thread (r = tid>>4, s = tid&15): sum_c abuf[r][c] * A[c*16+s] ----
    {
        int r = tid >> 4, s = tid & 15;
        const __nv_bfloat16* ar = ab + (size_t)r * APITCH;
        float acc = 0.f;
        #pragma unroll 8
        for (int c = 0; c < kDI; ++c)
            acc += __bfloat162float(ar[c]) * __ldg(&A[(size_t)c * kDS + s]);
        b1e[(size_t)(m0 + r) * kKE + kDI + s] = __float2bfloat16(acc);
    }
}

// C1[s,h] = sum_d Bm[s,d] * ha_w[h,d]
__global__ void c1_kernel(const float* __restrict__ Bm, const float* __restrict__ ha_w,
                          float* __restrict__ C1) {
    int g = (blockIdx.x * blockDim.x + threadIdx.x) >> 5;
    int lane = threadIdx.x & 31;
    if (g >= kDS * kD) return;
    int s = g >> 10, h = g & 1023;
    float acc = 0.f;
    const float* br = Bm + (size_t)s * kDI;
    const float* hr = ha_w + (size_t)h * kDI;
    for (int d = lane; d < kDI; d += 32) acc += br[d] * hr[d];
    #pragma unroll
    for (int o = 16; o; o >>= 1) acc += __shfl_xor_sync(~0u, acc, o);
    if (lane == 0) C1[(size_t)s * kD + h] = acc;
}

// C2[s,o] = sum_h C1[s,h]*F1[o,h]  ->  W3e[o*kKE + 2048 + s] (bf16)
__global__ void c2_kernel(const float* __restrict__ C1, const float* __restrict__ fuse_w,
                          __nv_bfloat16* __restrict__ W3e) {
    int g = (blockIdx.x * blockDim.x + threadIdx.x) >> 5;
    int lane = threadIdx.x & 31;
    if (g >= kDS * kDI) return;
    int s = g >> 11, o = g & (kDI - 1);
    float acc = 0.f;
    const float* cr = C1 + (size_t)s * kD;
    const float* fr = fuse_w + (size_t)o * kDI;
    for (int h = lane; h < kD; h += 32) acc += cr[h] * fr[h];
    #pragma unroll
    for (int q = 16; q; q >>= 1) acc += __shfl_xor_sync(~0u, acc, q);
    if (lane == 0) W3e[(size_t)o * kKE + kDI + s] = __float2bfloat16(acc);
}

// u[h] = sum_o1 hb_w[h,o1] * pw_b[o1]
__global__ void u_kernel(const float* __restrict__ hb_w, const float* __restrict__ pw_b,
                         float* __restrict__ u) {
    int h = (blockIdx.x * blockDim.x + threadIdx.x) >> 5;
    int lane = threadIdx.x & 31;
    if (h >= kD) return;
    float acc = 0.f;
    const float* hr = hb_w + (size_t)h * kDI;
    for (int o = lane; o < kDI; o += 32) acc += hr[o] * pw_b[o];
    #pragma unroll
    for (int q = 16; q; q >>= 1) acc += __shfl_xor_sync(~0u, acc, q);
    if (lane == 0) u[h] = acc;
}

// zb[o] = fuse_b[o] + sum_h( ha_b[h]*F1[o,h] + (hb_b[h]+u[h])*F2[o,h] )
__global__ void zbias_kernel(const float* __restrict__ fuse_b, const float* __restrict__ ha_b,
                             const float* __restrict__ hb_b, const float* __restrict__ u,
                             const float* __restrict__ fuse_w, float* __restrict__ zb) {
    int o = (blockIdx.x * blockDim.x + threadIdx.x) >> 5;
    int lane = threadIdx.x & 31;
    if (o >= kDI) return;
    float acc = 0.f;
    const float* fr = fuse_w + (size_t)o * kDI;
    for (int h = lane; h < kD; h += 32)
        acc += ha_b[h] * fr[h] + (hb_b[h] + u[h]) * fr[kD + h];
    #pragma unroll
    for (int q = 16; q; q >>= 1) acc += __shfl_xor_sync(~0u, acc, q);
    if (lane == 0) zb[o] = fuse_b[o] + acc;
}

// ==================== bf16 mma.sync GEMM, 128x256x64, 3-stage, 1 sync/iter ========
// C[M,N] = A[M,K] @ B[N,K]^T + bias
// MODE 0: bf16 -> out0[m*ldc + n]  (no bias)
// MODE 1: sigmoid -> out0 if col<kDI else raw -> out1 (col-kDI); ldc=kDI
// MODE 2: bf16 -> out0 = (acc + bias) * gate[m*kDI+col]
// MODE 3: outF = resid + acc + bias (fp32)
constexpr int BM = 128, BN = 256, BK = 64, LDS = BK + 8;
constexpr int NROWS = BM + BN;
constexpr int NSTG  = 3;
constexpr int STG_ELEMS = NROWS * LDS;
constexpr size_t SMEM_G = (size_t)NSTG * STG_ELEMS * 2;     // 165888 B

template<int MODE>
__global__ __launch_bounds__(256, 1)
void gemm_bf16(const __nv_bfloat16* __restrict__ Ag,
               const __nv_bfloat16* __restrict__ Bg,
               const float* __restrict__ bias,
               int K, int lda, int ldb,
               __nv_bfloat16* __restrict__ out0,
               __nv_bfloat16* __restrict__ out1,
               const __nv_bfloat16* __restrict__ gate,
               const float* __restrict__ resid,
               float* __restrict__ outF,
               int ldc) {
    extern __shared__ __align__(16) __nv_bfloat16 sm[];
    const int tid  = threadIdx.x;
    const int lane = tid & 31;
    const int warp = tid >> 5;
    const int wm = warp >> 2, wn = warp & 3;
    const int mBase = blockIdx.y * BM;
    const int nBase = blockIdx.x * BN;
    const int KT = K / BK;

    float c[4][8][4];
    #pragma unroll
    for (int i = 0; i < 4; ++i)
        #pragma unroll
        for (int j = 0; j < 8; ++j)
            #pragma unroll
            for (int q = 0; q < 4; ++q) c[i][j][q] = 0.f;

    auto load_tile = [&](int kt, int st) {
        __nv_bfloat16* dst = sm + (size_t)st * STG_ELEMS;
        int k0 = kt * BK;
        #pragma unroll
        for (int i = 0; i < 12; ++i) {
            int lin = tid + i * 256;
            int r = lin >> 3, cc = (lin & 7) << 3;
            const __nv_bfloat16* src = (r < BM)
                ? Ag + (size_t)(mBase + r) * lda + k0 + cc
                : Bg + (size_t)(nBase + r - BM) * ldb + k0 + cc;
            cp_async16(dst + r * LDS + cc, src);
        }
        cp_commit();
    };

    load_tile(0, 0);
    load_tile(1, 1);

    for (int kt = 0; kt < KT; ++kt) {
        cp_wait_group<1>();
        __syncthreads();                       // single barrier per iteration
        int st = kt % NSTG;
        if (kt + 2 < KT) load_tile(kt + 2, (kt + 2) % NSTG);
        else cp_commit();
        const __nv_bfloat16* As = sm + (size_t)st * STG_ELEMS;
        const __nv_bfloat16* Bs = As + BM * LDS;

        #pragma unroll
        for (int k16 = 0; k16 < 4; ++k16) {
            uint32_t af[4][4];
            #pragma unroll
            for (int mi = 0; mi < 4; ++mi) {
                int row = wm * 64 + mi * 16 + (lane & 15);
                int col = k16 * 16 + ((lane >> 4) << 3);
                uint32_t addr = (uint32_t)__cvta_generic_to_shared(&As[row * LDS + col]);
                asm volatile("ldmatrix.sync.aligned.m8n8.x4.shared.b16 {%0,%1,%2,%3}, [%4];"
                             : "=r"(af[mi][0]), "=r"(af[mi][1]), "=r"(af[mi][2]), "=r"(af[mi][3])
                             : "r"(addr));
            }
            uint32_t bfr[4][4];
            #pragma unroll
            for (int j = 0; j < 4; ++j) {
                int row = wn * 64 + j * 16 + ((lane >> 4) << 3) + (lane & 7);
                int col = k16 * 16 + (((lane >> 3) & 1) << 3);
                uint32_t addr = (uint32_t)__cvta_generic_to_shared(&Bs[row * LDS + col]);
                asm volatile("ldmatrix.sync.aligned.m8n8.x4.shared.b16 {%0,%1,%2,%3}, [%4];"
                             : "=r"(bfr[j][0]), "=r"(bfr[j][1]), "=r"(bfr[j][2]), "=r"(bfr[j][3])
                             : "r"(addr));
            }
            #pragma unroll
            for (int mi = 0; mi < 4; ++mi)
                #pragma unroll
                for (int ni = 0; ni < 8; ++ni) {
                    uint32_t b0 = bfr[ni >> 1][(ni & 1) * 2];
                    uint32_t b1 = bfr[ni >> 1][(ni & 1) * 2 + 1];
                    asm volatile("mma.sync.aligned.m16n8k16.row.col.f32.bf16.bf16.f32 "
                                 "{%0,%1,%2,%3}, {%4,%5,%6,%7}, {%8,%9}, {%0,%1,%2,%3};"
                                 : "+f"(c[mi][ni][0]), "+f"(c[mi][ni][1]),
                                   "+f"(c[mi][ni][2]), "+f"(c[mi][ni][3])
                                 : "r"(af[mi][0]), "r"(af[mi][1]), "r"(af[mi][2]), "r"(af[mi][3]),
                                   "r"(b0), "r"(b1));
                }
        }
    }

    // -------- epilogue --------
    const int g = lane >> 2, t = lane & 3;
    #pragma unroll
    for (int mi = 0; mi < 4; ++mi) {
        #pragma unroll
        for (int ni = 0; ni < 8; ++ni) {
            int col = nBase + wn * 64 + ni * 8 + t * 2;
            #pragma unroll
            for (int half = 0; half < 2; ++half) {
                int m = mBase + wm * 64 + mi * 16 + g + half * 8;
                float b0 = (MODE == 0) ? 0.f : bias[col];
                float b1v = (MODE == 0) ? 0.f : bias[col + 1];
                float v0 = c[mi][ni][half * 2 + 0] + b0;
                float v1 = c[mi][ni][half * 2 + 1] + b1v;
                if (MODE == 0) {
                    __nv_bfloat162 p;
                    p.x = __float2bfloat16(v0); p.y = __float2bfloat16(v1);
                    *reinterpret_cast<__nv_bfloat162*>(out0 + (size_t)m * ldc + col) = p;
                } else if (MODE == 1) {
                    if (col < kDI) {
                        __nv_bfloat162 p;
                        p.x = __float2bfloat16(1.f / (1.f + __expf(-v0)));
                        p.y = __float2bfloat16(1.f / (1.f + __expf(-v1)));
                        *reinterpret_cast<__nv_bfloat162*>(out0 + (size_t)m * kDI + col) = p;
                    } else {
                        __nv_bfloat162 p;
                        p.x = __float2bfloat16(v0); p.y = __float2bfloat16(v1);
                        *reinterpret_cast<__nv_bfloat162*>(out1 + (size_t)m * kDI + col - kDI) = p;
                    }
                } else if (MODE == 2) {
                    __nv_bfloat162 gp = *reinterpret_cast<const __nv_bfloat162*>(
                        gate + (size_t)m * kDI + col);
                    float2 fg = __bfloat1622float2(gp);
                    __nv_bfloat162 p;
                    p.x = __float2bfloat16(v0 * fg.x);
                    p.y = __float2bfloat16(v1 * fg.y);
                    *reinterpret_cast<__nv_bfloat162*>(out0 + (size_t)m * kDI + col) = p;
                } else {
                    const float2 r = *reinterpret_cast<const float2*>(resid + (size_t)m * ldc + col);
                    float2 o; o.x = r.x + v0; o.y = r.y + v1;
                    *reinterpret_cast<float2*>(outF + (size_t)m * ldc + col) = o;
                }
            }
        }
    }
}

// ==================== host ====================
extern "C" void kernel_launch(void* const* d_in, const int* in_sizes, int n_in,
                              void* d_out, int out_size) {
    const float* x      = (const float*)d_in[0];
    const float* norm_w = (const float*)d_in[1];
    const float* in_w   = (const float*)d_in[2];
    const float* in_b   = (const float*)d_in[3];
    const float* dwa_k  = (const float*)d_in[4];
    const float* dwa_b  = (const float*)d_in[5];
    const float* Amat   = (const float*)d_in[6];
    const float* Bm     = (const float*)d_in[7];
    const float* sym_k  = (const float*)d_in[8];
    const float* sym_b  = (const float*)d_in[9];
    const float* pw_w   = (const float*)d_in[10];
    const float* pw_b   = (const float*)d_in[11];
    const float* ha_w   = (const float*)d_in[12];
    const float* ha_b   = (const float*)d_in[13];
    const float* hb_w   = (const float*)d_in[14];
    const float* hb_b   = (const float*)d_in[15];
    const float* fuse_w = (const float*)d_in[16];
    const float* fuse_b = (const float*)d_in[17];
    const float* out_w  = (const float*)d_in[18];
    const float* out_b  = (const float*)d_in[19];
    float* out = (float*)d_out;

    __nv_bfloat16 *hn, *gateB, *valB, *b1e, *y2;
    __nv_bfloat16 *w_in, *w_fuse, *w_out, *hb_bf, *pwT, *U, *W3e;
    float *C1, *uvec, *zb;
    cudaGetSymbolAddress((void**)&hn,    g_hn);
    cudaGetSymbolAddress((void**)&gateB, g_gate);
    cudaGetSymbolAddress((void**)&valB,  g_val);
    cudaGetSymbolAddress((void**)&b1e,   g_b1e);
    cudaGetSymbolAddress((void**)&y2,    g_y2);
    cudaGetSymbolAddress((void**)&w_in,   g_w_in);
    cudaGetSymbolAddress((void**)&w_fuse, g_w_fuse);
    cudaGetSymbolAddress((void**)&w_out,  g_w_out);
    cudaGetSymbolAddress((void**)&hb_bf,  g_hb_bf);
    cudaGetSymbolAddress((void**)&pwT,    g_pwT);
    cudaGetSymbolAddress((void**)&U,      g_U);
    cudaGetSymbolAddress((void**)&W3e,    g_W3e);
    cudaGetSymbolAddress((void**)&C1,     g_C1);
    cudaGetSymbolAddress((void**)&uvec,   g_u);
    cudaGetSymbolAddress((void**)&zb,     g_zb);

    cudaFuncSetAttribute(gemm_bf16<0>, cudaFuncAttributeMaxDynamicSharedMemorySize, (int)SMEM_G);
    cudaFuncSetAttribute(gemm_bf16<1>, cudaFuncAttributeMaxDynamicSharedMemorySize, (int)SMEM_G);
    cudaFuncSetAttribute(gemm_bf16<2>, cudaFuncAttributeMaxDynamicSharedMemorySize, (int)SMEM_G);
    cudaFuncSetAttribute(gemm_bf16<3>, cudaFuncAttributeMaxDynamicSharedMemorySize, (int)SMEM_G);
    cudaFuncSetAttribute(dwconv2_kernel, cudaFuncAttributeMaxDynamicSharedMemorySize, (int)DSM_DW);

    // 0-3: rmsnorm + conversions needed by in-GEMM
    rmsnorm_kernel<<<kM, 256>>>(x, norm_w, hn);
    f2bf_kernel<<<1024, 256>>>((const float4*)in_w,   (uint2*)w_in,   (2*kDI*kD)/4);
    f2bf_kernel<<<1024, 256>>>((const float4*)fuse_w, (uint2*)w_fuse, (kDI*kDI)/4);
    f2bf_kernel<<<512,  256>>>((const float4*)out_w,  (uint2*)w_out,  (kD*kDI)/4);

    // 4: in-proj GEMM
    gemm_bf16<1><<<dim3((2*kDI)/BN, kM/BM), 256, SMEM_G>>>(
        hn, w_in, in_b, kD, kD, kD, gateB, valB, nullptr, nullptr, nullptr, kDI);

    // 5: fused dwconv + rank-16 a2 (writes b1e cols 0..2047 and 2048..2063)
    dwconv2_kernel<<<kM/TMR, 256, DSM_DW>>>(valB, dwa_k, dwa_b, sym_k, sym_b, Amat, b1e);

    // precompute chain for W3e
    f2bf_kernel<<<512, 256>>>((const float4*)hb_w, (uint2*)hb_bf, (kD*kDI)/4);
    transpose_f2bf<<<dim3(kDI/32, kDI/32), dim3(32,8)>>>(pw_w, pwT, kDI, kDI);
    // U = pwT @ hb_bf^T : [2048,1024]
    gemm_bf16<0><<<dim3(kD/BN, kDI/BM), 256, SMEM_G>>>(
        pwT, hb_bf, nullptr, kDI, kDI, kDI, U, nullptr, nullptr, nullptr, nullptr, kD);
    // W3e[:, :2048] = F2 @ U^T : [2048,2048], ldc = kKE
    gemm_bf16<0><<<dim3(kDI/BN, kDI/BM), 256, SMEM_G>>>(
        w_fuse + kD, U, nullptr, kD, kDI, kD, W3e, nullptr, nullptr, nullptr, nullptr, kKE);
    // bias folding
    u_kernel<<<(kD*32)/256, 256>>>(hb_w, pw_b, uvec);
    zbias_kernel<<<(kDI*32)/256, 256>>>(fuse_b, ha_b, hb_b, uvec, fuse_w, zb);
    // a-path rank-16 factors -> W3e cols 2048..2063
    c1_kernel<<<(kDS*kD*32)/256, 256>>>(Bm, ha_w, C1);
    c2_kernel<<<(kDS*kDI*32)/256, 256>>>(C1, fuse_w, W3e);

    // fuse GEMM (K = 2112, folded a-path + biases), gate-multiply epilogue
    gemm_bf16<2><<<dim3(kDI/BN, kM/BM), 256, SMEM_G>>>(
        b1e, W3e, zb, kKE, kKE, kKE, y2, nullptr, gateB, nullptr, nullptr, kDI);

    // out-proj with residual add, fp32 out
    gemm_bf16<3><<<dim3(kD/BN, kM/BM), 256, SMEM_G>>>(
        y2, w_out, out_b, kDI, kDI, kDI, nullptr, nullptr, nullptr, x, out, kD);
}

// round 16
// speedup vs baseline: 1.4933x; 1.0361x over previous
#include <cuda_runtime.h>
#include <cuda_bf16.h>
#include <cstdint>

constexpr int kL  = 4096;
constexpr int kD  = 1024;
constexpr int kDI = 2048;
constexpr int kM  = 4 * kL;           // 16384
constexpr int kDS = 16;
constexpr int kKE = kDI + 64;         // 2112: K-extended (b1 | a2 | zeros)

// ---------------- static scratch (zero-initialized; pad columns never written) ----
__device__ __align__(256) __nv_bfloat16 g_hn   [(size_t)kM * kD];
__device__ __align__(256) __nv_bfloat16 g_gate [(size_t)kM * kDI];
__device__ __align__(256) __nv_bfloat16 g_val  [(size_t)kM * kDI];
__device__ __align__(256) __nv_bfloat16 g_b1e  [(size_t)kM * kKE];     // [b1 | a2 | 0]
__device__ __align__(256) __nv_bfloat16 g_y2   [(size_t)kM * kDI];
__device__ __align__(256) __nv_bfloat16 g_w_in [(size_t)2*kDI * kD];
__device__ __align__(256) __nv_bfloat16 g_w_fuse[(size_t)kDI * kDI];
__device__ __align__(256) __nv_bfloat16 g_w_out[(size_t)kD * kDI];
__device__ __align__(256) __nv_bfloat16 g_hb_bf[(size_t)kD * kDI];
__device__ __align__(256) __nv_bfloat16 g_pwT  [(size_t)kDI * kDI];
__device__ __align__(256) __nv_bfloat16 g_U    [(size_t)kDI * kD];     // (hb_w@pw_w)^T [2048,1024]
__device__ __align__(256) __nv_bfloat16 g_W3e  [(size_t)kDI * kKE];    // [W3 | C2^T | 0]
__device__ __align__(256) float         g_C1   [(size_t)kDS * kD];
__device__ float g_u [kD];
__device__ float g_zb[kDI];

#define DEVFN __device__ __forceinline__

DEVFN void cp_async16(void* smem, const void* gmem) {
    uint32_t a = (uint32_t)__cvta_generic_to_shared(smem);
    asm volatile("cp.async.cg.shared.global [%0], [%1], 16;" :: "r"(a), "l"(gmem));
}
DEVFN void cp_commit() { asm volatile("cp.async.commit_group;"); }
template<int N> DEVFN void cp_wait_group() { asm volatile("cp.async.wait_group %0;" :: "n"(N)); }

// ---------------- conversion / elementwise kernels ----------------
__global__ void f2bf_kernel(const float4* __restrict__ s, uint2* __restrict__ d, int n4) {
    int i = blockIdx.x * blockDim.x + threadIdx.x, st = gridDim.x * blockDim.x;
    for (; i < n4; i += st) {
        float4 v = s[i];
        __nv_bfloat162 lo = __floats2bfloat162_rn(v.x, v.y);
        __nv_bfloat162 hi = __floats2bfloat162_rn(v.z, v.w);
        uint2 o; o.x = *(uint32_t*)&lo; o.y = *(uint32_t*)&hi;
        d[i] = o;
    }
}

// transpose fp32 [R,C] -> bf16 [C,R]
__global__ void transpose_f2bf(const float* __restrict__ src, __nv_bfloat16* __restrict__ dst,
                               int R, int C) {
    __shared__ float t[32][33];
    int c0 = blockIdx.x * 32, r0 = blockIdx.y * 32;
    int x = threadIdx.x;
    #pragma unroll
    for (int y = threadIdx.y; y < 32; y += 8)
        t[y][x] = src[(size_t)(r0 + y) * C + c0 + x];
    __syncthreads();
    #pragma unroll
    for (int y = threadIdx.y; y < 32; y += 8)
        dst[(size_t)(c0 + y) * R + r0 + x] = __float2bfloat16(t[x][y]);
}

__global__ void rmsnorm_kernel(const float* __restrict__ x, const float* __restrict__ w,
                               __nv_bfloat16* __restrict__ out) {
    int m = blockIdx.x;
    const float* xr = x + (size_t)m * kD;
    float ss = 0.f;
    for (int c = threadIdx.x; c < kD; c += 256) { float v = xr[c]; ss += v * v; }
    #pragma unroll
    for (int o = 16; o; o >>= 1) ss += __shfl_xor_sync(~0u, ss, o);
    __shared__ float red[8];
    if ((threadIdx.x & 31) == 0) red[threadIdx.x >> 5] = ss;
    __syncthreads();
    float tot = 0.f;
    #pragma unroll
    for (int i = 0; i < 8; ++i) tot += red[i];
    float sc = rsqrtf(tot * (1.f / kD) + 1e-6f);
    for (int c = threadIdx.x; c < kD; c += 256)
        out[(size_t)m * kD + c] = __float2bfloat16(w[c] * xr[c] * sc);
}

// ==================== fused dwconv + low-rank a2, SMEM-tiled ====================
constexpr int TMR   = 16;
constexpr int VROWS = TMR + 8;            // 24
constexpr int APITCH = kDI + 8;           // 2056 (bank-skew pad)
constexpr size_t DSM_DW = (size_t)VROWS * kDI * 2 + (size_t)TMR * APITCH * 2;  // 164096 B

__global__ __launch_bounds__(256, 1)
void dwconv2_kernel(const __nv_bfloat16* __restrict__ val,
                    const float* __restrict__ k4, const float* __restrict__ b4,
                    const float* __restrict__ k9, const float* __restrict__ b9,
                    const float* __restrict__ A,
                    __nv_bfloat16* __restrict__ b1e) {
    extern __shared__ __align__(16) char ds[];
    __nv_bfloat16* vt = reinterpret_cast<__nv_bfloat16*>(ds);                       // [24][2048]
    __nv_bfloat16* ab = reinterpret_cast<__nv_bfloat16*>(ds + (size_t)VROWS * kDI * 2); // [16][2056]
    const int tid = threadIdx.x;
    const int m0 = blockIdx.x * TMR;
    const int l0 = m0 & (kL - 1);

    #pragma unroll
    for (int vr = 0; vr < VROWS; ++vr) {
        int l = l0 - 4 + vr;
        void* dst = vt + (size_t)vr * kDI + tid * 8;
        if (l >= 0 && l < kL)
            cp_async16(dst, val + (size_t)(m0 - 4 + vr) * kDI + tid * 8);
        else
            *reinterpret_cast<uint4*>(dst) = make_uint4(0, 0, 0, 0);
    }
    cp_commit();
    cp_wait_group<0>();
    __syncthreads();

    #pragma unroll 1
    for (int k = 0; k < 8; ++k) {
        int c = tid + k * 256;
        float w4[4], w9[9];
        #pragma unroll
        for (int t = 0; t < 4; ++t) w4[t] = k4[c * 4 + t];
        #pragma unroll
        for (int t = 0; t < 9; ++t) w9[t] = k9[c * 9 + t];
        float bb4 = b4[c], bb9 = b9[c];
        float v[VROWS];
        #pragma unroll
        for (int r = 0; r < VROWS; ++r) v[r] = __bfloat162float(vt[(size_t)r * kDI + c]);
        #pragma unroll
        for (int ro = 0; ro < TMR; ++ro) {
            float a = bb4;
            #pragma unroll
            for (int t = 0; t < 4; ++t) a += v[ro + 3 + t] * w4[t];
            float b = bb9;
            #pragma unroll
            for (int t = 0; t < 9; ++t) b += v[ro + t] * w9[t];
            b1e[(size_t)(m0 + ro) * kKE + c] = __float2bfloat16(b / (1.f + __expf(-b)));
            ab[(size_t)ro * APITCH + c] = __float2bfloat16(a);
        }
    }
    __syncthreads();

    {
        int r = tid >> 4, s = tid & 15;
        const __nv_bfloat16* ar = ab + (size_t)r * APITCH;
        float acc = 0.f;
        #pragma unroll 8
        for (int c = 0; c < kDI; ++c)
            acc += __bfloat162float(ar[c]) * __ldg(&A[(size_t)c * kDS + s]);
        b1e[(size_t)(m0 + r) * kKE + kDI + s] = __float2bfloat16(acc);
    }
}

// C1[s,h] = sum_d Bm[s,d] * ha_w[h,d]
__global__ void c1_kernel(const float* __restrict__ Bm, const float* __restrict__ ha_w,
                          float* __restrict__ C1) {
    int g = (blockIdx.x * blockDim.x + threadIdx.x) >> 5;
    int lane = threadIdx.x & 31;
    if (g >= kDS * kD) return;
    int s = g >> 10, h = g & 1023;
    float acc = 0.f;
    const float* br = Bm + (size_t)s * kDI;
    const float* hr = ha_w + (size_t)h * kDI;
    for (int d = lane; d < kDI; d += 32) acc += br[d] * hr[d];
    #pragma unroll
    for (int o = 16; o; o >>= 1) acc += __shfl_xor_sync(~0u, acc, o);
    if (lane == 0) C1[(size_t)s * kD + h] = acc;
}

// C2[s,o] = sum_h C1[s,h]*F1[o,h]  ->  W3e[o*kKE + 2048 + s] (bf16)
__global__ void c2_kernel(const float* __restrict__ C1, const float* __restrict__ fuse_w,
                          __nv_bfloat16* __restrict__ W3e) {
    int g = (blockIdx.x * blockDim.x + threadIdx.x) >> 5;
    int lane = threadIdx.x & 31;
    if (g >= kDS * kDI) return;
    int s = g >> 11, o = g & (kDI - 1);
    float acc = 0.f;
    const float* cr = C1 + (size_t)s * kD;
    const float* fr = fuse_w + (size_t)o * kDI;
    for (int h = lane; h < kD; h += 32) acc += cr[h] * fr[h];
    #pragma unroll
    for (int q = 16; q; q >>= 1) acc += __shfl_xor_sync(~0u, acc, q);
    if (lane == 0) W3e[(size_t)o * kKE + kDI + s] = __float2bfloat16(acc);
}

// u[h] = sum_o1 hb_w[h,o1] * pw_b[o1]
__global__ void u_kernel(const float* __restrict__ hb_w, const float* __restrict__ pw_b,
                         float* __restrict__ u) {
    int h = (blockIdx.x * blockDim.x + threadIdx.x) >> 5;
    int lane = threadIdx.x & 31;
    if (h >= kD) return;
    float acc = 0.f;
    const float* hr = hb_w + (size_t)h * kDI;
    for (int o = lane; o < kDI; o += 32) acc += hr[o] * pw_b[o];
    #pragma unroll
    for (int q = 16; q; q >>= 1) acc += __shfl_xor_sync(~0u, acc, q);
    if (lane == 0) u[h] = acc;
}

// zb[o] = fuse_b[o] + sum_h( ha_b[h]*F1[o,h] + (hb_b[h]+u[h])*F2[o,h] )
__global__ void zbias_kernel(const float* __restrict__ fuse_b, const float* __restrict__ ha_b,
                             const float* __restrict__ hb_b, const float* __restrict__ u,
                             const float* __restrict__ fuse_w, float* __restrict__ zb) {
    int o = (blockIdx.x * blockDim.x + threadIdx.x) >> 5;
    int lane = threadIdx.x & 31;
    if (o >= kDI) return;
    float acc = 0.f;
    const float* fr = fuse_w + (size_t)o * kDI;
    for (int h = lane; h < kD; h += 32)
        acc += ha_b[h] * fr[h] + (hb_b[h] + u[h]) * fr[kD + h];
    #pragma unroll
    for (int q = 16; q; q >>= 1) acc += __shfl_xor_sync(~0u, acc, q);
    if (lane == 0) zb[o] = fuse_b[o] + acc;
}

// ==================== bf16 mma.sync GEMM, 128x256x64, 3-stage, 1 sync/iter ========
constexpr int BM = 128, BN = 256, BK = 64, LDS = BK + 8;
constexpr int NROWS = BM + BN;
constexpr int NSTG  = 3;
constexpr int STG_ELEMS = NROWS * LDS;
constexpr size_t SMEM_G = (size_t)NSTG * STG_ELEMS * 2;     // 165888 B

template<int MODE>
__global__ __launch_bounds__(256, 1)
void gemm_bf16(const __nv_bfloat16* __restrict__ Ag,
               const __nv_bfloat16* __restrict__ Bg,
               const float* __restrict__ bias,
               int K, int lda, int ldb,
               __nv_bfloat16* __restrict__ out0,
               __nv_bfloat16* __restrict__ out1,
               const __nv_bfloat16* __restrict__ gate,
               const float* __restrict__ resid,
               float* __restrict__ outF,
               int ldc) {
    extern __shared__ __align__(16) __nv_bfloat16 sm[];
    const int tid  = threadIdx.x;
    const int lane = tid & 31;
    const int warp = tid >> 5;
    const int wm = warp >> 2, wn = warp & 3;
    const int mBase = blockIdx.y * BM;
    const int nBase = blockIdx.x * BN;
    const int KT = K / BK;

    float c[4][8][4];
    #pragma unroll
    for (int i = 0; i < 4; ++i)
        #pragma unroll
        for (int j = 0; j < 8; ++j)
            #pragma unroll
            for (int q = 0; q < 4; ++q) c[i][j][q] = 0.f;

    auto load_tile = [&](int kt, int st) {
        __nv_bfloat16* dst = sm + (size_t)st * STG_ELEMS;
        int k0 = kt * BK;
        #pragma unroll
        for (int i = 0; i < 12; ++i) {
            int lin = tid + i * 256;
            int r = lin >> 3, cc = (lin & 7) << 3;
            const __nv_bfloat16* src = (r < BM)
                ? Ag + (size_t)(mBase + r) * lda + k0 + cc
                : Bg + (size_t)(nBase + r - BM) * ldb + k0 + cc;
            cp_async16(dst + r * LDS + cc, src);
        }
        cp_commit();
    };

    load_tile(0, 0);
    load_tile(1, 1);

    for (int kt = 0; kt < KT; ++kt) {
        cp_wait_group<1>();
        __syncthreads();                       // single barrier per iteration
        int st = kt % NSTG;
        if (kt + 2 < KT) load_tile(kt + 2, (kt + 2) % NSTG);
        else cp_commit();
        const __nv_bfloat16* As = sm + (size_t)st * STG_ELEMS;
        const __nv_bfloat16* Bs = As + BM * LDS;

        #pragma unroll
        for (int k16 = 0; k16 < 4; ++k16) {
            uint32_t af[4][4];
            #pragma unroll
            for (int mi = 0; mi < 4; ++mi) {
                int row = wm * 64 + mi * 16 + (lane & 15);
                int col = k16 * 16 + ((lane >> 4) << 3);
                uint32_t addr = (uint32_t)__cvta_generic_to_shared(&As[row * LDS + col]);
                asm volatile("ldmatrix.sync.aligned.m8n8.x4.shared.b16 {%0,%1,%2,%3}, [%4];"
                             : "=r"(af[mi][0]), "=r"(af[mi][1]), "=r"(af[mi][2]), "=r"(af[mi][3])
                             : "r"(addr));
            }
            uint32_t bfr[4][4];
            #pragma unroll
            for (int j = 0; j < 4; ++j) {
                int row = wn * 64 + j * 16 + ((lane >> 4) << 3) + (lane & 7);
                int col = k16 * 16 + (((lane >> 3) & 1) << 3);
                uint32_t addr = (uint32_t)__cvta_generic_to_shared(&Bs[row * LDS + col]);
                asm volatile("ldmatrix.sync.aligned.m8n8.x4.shared.b16 {%0,%1,%2,%3}, [%4];"
                             : "=r"(bfr[j][0]), "=r"(bfr[j][1]), "=r"(bfr[j][2]), "=r"(bfr[j][3])
                             : "r"(addr));
            }
            #pragma unroll
            for (int mi = 0; mi < 4; ++mi)
                #pragma unroll
                for (int ni = 0; ni < 8; ++ni) {
                    uint32_t b0 = bfr[ni >> 1][(ni & 1) * 2];
                    uint32_t b1 = bfr[ni >> 1][(ni & 1) * 2 + 1];
                    asm volatile("mma.sync.aligned.m16n8k16.row.col.f32.bf16.bf16.f32 "
                                 "{%0,%1,%2,%3}, {%4,%5,%6,%7}, {%8,%9}, {%0,%1,%2,%3};"
                                 : "+f"(c[mi][ni][0]), "+f"(c[mi][ni][1]),
                                   "+f"(c[mi][ni][2]), "+f"(c[mi][ni][3])
                                 : "r"(af[mi][0]), "r"(af[mi][1]), "r"(af[mi][2]), "r"(af[mi][3]),
                                   "r"(b0), "r"(b1));
                }
        }
    }

    // -------- epilogue --------
    const int g = lane >> 2, t = lane & 3;
    #pragma unroll
    for (int mi = 0; mi < 4; ++mi) {
        #pragma unroll
        for (int ni = 0; ni < 8; ++ni) {
            int col = nBase + wn * 64 + ni * 8 + t * 2;
            #pragma unroll
            for (int half = 0; half < 2; ++half) {
                int m = mBase + wm * 64 + mi * 16 + g + half * 8;
                float b0 = (MODE == 0) ? 0.f : bias[col];
                float b1v = (MODE == 0) ? 0.f : bias[col + 1];
                float v0 = c[mi][ni][half * 2 + 0] + b0;
                float v1 = c[mi][ni][half * 2 + 1] + b1v;
                if (MODE == 0) {
                    __nv_bfloat162 p;
                    p.x = __float2bfloat16(v0); p.y = __float2bfloat16(v1);
                    *reinterpret_cast<__nv_bfloat162*>(out0 + (size_t)m * ldc + col) = p;
                } else if (MODE == 1) {
                    if (col < kDI) {
                        __nv_bfloat162 p;
                        p.x = __float2bfloat16(1.f / (1.f + __expf(-v0)));
                        p.y = __float2bfloat16(1.f / (1.f + __expf(-v1)));
                        *reinterpret_cast<__nv_bfloat162*>(out0 + (size_t)m * kDI + col) = p;
                    } else {
                        __nv_bfloat162 p;
                        p.x = __float2bfloat16(v0); p.y = __float2bfloat16(v1);
                        *reinterpret_cast<__nv_bfloat162*>(out1 + (size_t)m * kDI + col - kDI) = p;
                    }
                } else if (MODE == 2) {
                    __nv_bfloat162 gp = *reinterpret_cast<const __nv_bfloat162*>(
                        gate + (size_t)m * kDI + col);
                    float2 fg = __bfloat1622float2(gp);
                    __nv_bfloat162 p;
                    p.x = __float2bfloat16(v0 * fg.x);
                    p.y = __float2bfloat16(v1 * fg.y);
                    *reinterpret_cast<__nv_bfloat162*>(out0 + (size_t)m * kDI + col) = p;
                } else {
                    const float2 r = *reinterpret_cast<const float2*>(resid + (size_t)m * ldc + col);
                    float2 o; o.x = r.x + v0; o.y = r.y + v1;
                    *reinterpret_cast<float2*>(outF + (size_t)m * ldc + col) = o;
                }
            }
        }
    }
}

// ==================== host ====================
extern "C" void kernel_launch(void* const* d_in, const int* in_sizes, int n_in,
                              void* d_out, int out_size) {
    const float* x      = (const float*)d_in[0];
    const float* norm_w = (const float*)d_in[1];
    const float* in_w   = (const float*)d_in[2];
    const float* in_b   = (const float*)d_in[3];
    const float* dwa_k  = (const float*)d_in[4];
    const float* dwa_b  = (const float*)d_in[5];
    const float* Amat   = (const float*)d_in[6];
    const float* Bm     = (const float*)d_in[7];
    const float* sym_k  = (const float*)d_in[8];
    const float* sym_b  = (const float*)d_in[9];
    const float* pw_w   = (const float*)d_in[10];
    const float* pw_b   = (const float*)d_in[11];
    const float* ha_w   = (const float*)d_in[12];
    const float* ha_b   = (const float*)d_in[13];
    const float* hb_w   = (const float*)d_in[14];
    const float* hb_b   = (const float*)d_in[15];
    const float* fuse_w = (const float*)d_in[16];
    const float* fuse_b = (const float*)d_in[17];
    const float* out_w  = (const float*)d_in[18];
    const float* out_b  = (const float*)d_in[19];
    float* out = (float*)d_out;

    __nv_bfloat16 *hn, *gateB, *valB, *b1e, *y2;
    __nv_bfloat16 *w_in, *w_fuse, *w_out, *hb_bf, *pwT, *U, *W3e;
    float *C1, *uvec, *zb;
    cudaGetSymbolAddress((void**)&hn,    g_hn);
    cudaGetSymbolAddress((void**)&gateB, g_gate);
    cudaGetSymbolAddress((void**)&valB,  g_val);
    cudaGetSymbolAddress((void**)&b1e,   g_b1e);
    cudaGetSymbolAddress((void**)&y2,    g_y2);
    cudaGetSymbolAddress((void**)&w_in,   g_w_in);
    cudaGetSymbolAddress((void**)&w_fuse, g_w_fuse);
    cudaGetSymbolAddress((void**)&w_out,  g_w_out);
    cudaGetSymbolAddress((void**)&hb_bf,  g_hb_bf);
    cudaGetSymbolAddress((void**)&pwT,    g_pwT);
    cudaGetSymbolAddress((void**)&U,      g_U);
    cudaGetSymbolAddress((void**)&W3e,    g_W3e);
    cudaGetSymbolAddress((void**)&C1,     g_C1);
    cudaGetSymbolAddress((void**)&uvec,   g_u);
    cudaGetSymbolAddress((void**)&zb,     g_zb);

    cudaFuncSetAttribute(gemm_bf16<0>, cudaFuncAttributeMaxDynamicSharedMemorySize, (int)SMEM_G);
    cudaFuncSetAttribute(gemm_bf16<1>, cudaFuncAttributeMaxDynamicSharedMemorySize, (int)SMEM_G);
    cudaFuncSetAttribute(gemm_bf16<2>, cudaFuncAttributeMaxDynamicSharedMemorySize, (int)SMEM_G);
    cudaFuncSetAttribute(gemm_bf16<3>, cudaFuncAttributeMaxDynamicSharedMemorySize, (int)SMEM_G);
    cudaFuncSetAttribute(dwconv2_kernel, cudaFuncAttributeMaxDynamicSharedMemorySize, (int)DSM_DW);

    // one-time side stream + fork/join events (created on first call, reused; no
    // device-memory allocation APIs involved; per-call captured work is identical)
    static cudaStream_t s_side = nullptr;
    static cudaEvent_t evFork = nullptr, evJoin = nullptr;
    if (s_side == nullptr) {
        cudaStreamCreateWithFlags(&s_side, cudaStreamNonBlocking);
        cudaEventCreateWithFlags(&evFork, cudaEventDisableTiming);
        cudaEventCreateWithFlags(&evJoin, cudaEventDisableTiming);
    }

    // ---- fork: side stream inherits capture from the main (legacy) stream ----
    cudaEventRecord(evFork, 0);
    cudaStreamWaitEvent(s_side, evFork, 0);

    // ---- side chain: precompute W3e / zb / conversions not needed until fuse ----
    f2bf_kernel<<<1024, 256, 0, s_side>>>((const float4*)fuse_w, (uint2*)w_fuse, (kDI*kDI)/4);
    f2bf_kernel<<<512,  256, 0, s_side>>>((const float4*)out_w,  (uint2*)w_out,  (kD*kDI)/4);
    f2bf_kernel<<<512,  256, 0, s_side>>>((const float4*)hb_w,   (uint2*)hb_bf,  (kD*kDI)/4);
    transpose_f2bf<<<dim3(kDI/32, kDI/32), dim3(32,8), 0, s_side>>>(pw_w, pwT, kDI, kDI);
    // U = pwT @ hb_bf^T : [2048,1024]
    gemm_bf16<0><<<dim3(kD/BN, kDI/BM), 256, SMEM_G, s_side>>>(
        pwT, hb_bf, nullptr, kDI, kDI, kDI, U, nullptr, nullptr, nullptr, nullptr, kD);
    // W3e[:, :2048] = F2 @ U^T : [2048,2048], ldc = kKE
    gemm_bf16<0><<<dim3(kDI/BN, kDI/BM), 256, SMEM_G, s_side>>>(
        w_fuse + kD, U, nullptr, kD, kDI, kD, W3e, nullptr, nullptr, nullptr, nullptr, kKE);
    u_kernel<<<(kD*32)/256, 256, 0, s_side>>>(hb_w, pw_b, uvec);
    zbias_kernel<<<(kDI*32)/256, 256, 0, s_side>>>(fuse_b, ha_b, hb_b, uvec, fuse_w, zb);
    c1_kernel<<<(kDS*kD*32)/256, 256, 0, s_side>>>(Bm, ha_w, C1);
    c2_kernel<<<(kDS*kDI*32)/256, 256, 0, s_side>>>(C1, fuse_w, W3e);
    cudaEventRecord(evJoin, s_side);

    // ---- main chain: critical path ----
    rmsnorm_kernel<<<kM, 256>>>(x, norm_w, hn);
    f2bf_kernel<<<1024, 256>>>((const float4*)in_w, (uint2*)w_in, (2*kDI*kD)/4);

    gemm_bf16<1><<<dim3((2*kDI)/BN, kM/BM), 256, SMEM_G>>>(
        hn, w_in, in_b, kD, kD, kD, gateB, valB, nullptr, nullptr, nullptr, kDI);

    dwconv2_kernel<<<kM/TMR, 256, DSM_DW>>>(valB, dwa_k, dwa_b, sym_k, sym_b, Amat, b1e);

    // ---- join: fuse needs W3e/zb from side chain ----
    cudaStreamWaitEvent(0, evJoin, 0);

    // fuse GEMM (K = 2112, folded a-path + biases), gate-multiply epilogue
    gemm_bf16<2><<<dim3(kDI/BN, kM/BM), 256, SMEM_G>>>(
        b1e, W3e, zb, kKE, kKE, kKE, y2, nullptr, gateB, nullptr, nullptr, kDI);

    // out-proj with residual add, fp32 out
    gemm_bf16<3><<<dim3(kD/BN, kM/BM), 256, SMEM_G>>>(
        y2, w_out, out_b, kDI, kDI, kDI, nullptr, nullptr, nullptr, x, out, kD);
}